// round 12
// baseline (speedup 1.0000x reference)
#include <cuda_runtime.h>
#include <cstdint>
#include <math.h>

#define ALPHA_CELU 0.1f

// ---------------- device scratch ----------------
__device__ float g_Wp0[4 * 24 * 256 * 16];   // [s][chunk][n][16 perm k]
__device__ float g_Wp1[4 * 16 * 192 * 16];
__device__ float g_Wp2[4 * 12 * 160 * 16];
__device__ float g_partial[256 * 1024];      // [atom][b]
__device__ float g_red[8 * 1024];

// ---------------- helpers ----------------
// Branchless CELU: max(x,0) + min(0, alpha*(exp(x/alpha)-1)).
__device__ __forceinline__ float celu_f(float x) {
    float e = __expf(x * (1.f / ALPHA_CELU));
    return fmaxf(x, 0.f) + fminf(0.f, ALPHA_CELU * (e - 1.f));
}
__device__ __forceinline__ uint32_t tf32r(float x) {   // RNA round to tf32
    uint32_t u;
    asm("cvt.rna.tf32.f32 %0, %1;" : "=r"(u) : "f"(x));
    return u;
}
__device__ __forceinline__ float tf32rf(float x) { return __uint_as_float(tf32r(x)); }
__device__ __forceinline__ uint32_t smem_u32(const void* p) {
    uint32_t a;
    asm("{ .reg .u64 t; cvta.to.shared.u64 t, %1; cvt.u32.u64 %0, t; }" : "=r"(a) : "l"(p));
    return a;
}
__device__ __forceinline__ void mma_tf32(float c[4],
                                         uint32_t a0, uint32_t a1, uint32_t a2, uint32_t a3,
                                         uint32_t b0, uint32_t b1) {
    asm volatile("mma.sync.aligned.m16n8k8.row.col.f32.tf32.tf32.f32 "
                 "{%0,%1,%2,%3}, {%4,%5,%6,%7}, {%8,%9}, {%0,%1,%2,%3};"
                 : "+f"(c[0]), "+f"(c[1]), "+f"(c[2]), "+f"(c[3])
                 : "r"(a0), "r"(a1), "r"(a2), "r"(a3), "r"(b0), "r"(b1));
}
#define CP_ASYNC16(dst, src) \
    asm volatile("cp.async.ca.shared.global [%0], [%1], 16;" :: "r"(dst), "l"(src))
#define CP_COMMIT() asm volatile("cp.async.commit_group;" ::: "memory")
#define CP_WAIT1()  asm volatile("cp.async.wait_group 1;" ::: "memory")
#define CP_WAIT2()  asm volatile("cp.async.wait_group 2;" ::: "memory")

// ---------------- smem layout (floats) ----------------
// Ys: 128 x 272.  X ring (L0 only, 4 slots x 2560 floats, row stride 20, PERMUTED k)
// OVERLAYS Ys.  W ring: 4 slots x 4096 floats after Ys.
#define LDY 272
#define OFF_W (128 * LDY)                 // 34816 floats
#define SMEM_FLOATS (OFF_W + 4 * 4096)    // 51200 floats
#define SMEM_BYTES (SMEM_FLOATS * 4)      // 204800 B

// ---------------- weight prep: [S,K,N] -> [s][k/16][n][perm(k&15)] tf32 ----------------
template<int K, int N, int WHICH>
__global__ void prep_w(const float* __restrict__ W) {
    int i = blockIdx.x * blockDim.x + threadIdx.x;
    if (i >= 4 * K * N) return;
    float* dst = (WHICH == 0) ? g_Wp0 : (WHICH == 1) ? g_Wp1 : g_Wp2;
    int n = i % N, k = (i / N) % K, s = i / (N * K);
    int chunk = k >> 4, w = k & 15;
    int p = ((w & 3) << 2) | (w >> 2);
    dst[((size_t)(s * (K / 16) + chunk) * N + n) * 16 + p] = __uint_as_float(tf32r(W[i]));
}

// ---------------- one layer (512 threads, warp grid 4m x 4n, warp tile 32 x N/4) ----------------
template<int K, int N, bool IS_L0, bool ROUND>
__device__ __forceinline__ void layer_run(
    const float* __restrict__ Wp, const float* __restrict__ bg,
    const float* __restrict__ xg,
    float* __restrict__ Ys, const float* __restrict__ WcF, float* __restrict__ Xc,
    uint32_t wcU,
    int tid, int lane, int m_idx, int n_idx)
{
    constexpr int NT = N / 32;                // n8 tiles per warp (8 / 6 / 5)
    constexpr int NC = K / 16;
    constexpr int WI = (N * 4 + 511) / 512;   // W float4s per thread per chunk

    float acc[2][NT][4];
#pragma unroll
    for (int f = 0; f < 2; f++)
#pragma unroll
        for (int t = 0; t < NT; t++)
#pragma unroll
            for (int j = 0; j < 4; j++) acc[f][t][j] = 0.f;

    const int xrow = tid >> 2, xblk = tid & 3;   // 512 thr = 128 rows x 4 k-quads

    // W staging via cp.async (unchanged from R10)
    auto stageW = [&](int c) {
        const char* wsrc = (const char*)(Wp + (size_t)c * N * 16);
        const uint32_t wdst = wcU + (uint32_t)(c & 3) * 16384u;
#pragma unroll
        for (int j = 0; j < WI; j++) {
            int i = tid + j * 512;
            if ((N * 4) % 512 == 0 || i < N * 4)
                CP_ASYNC16(wdst + (uint32_t)i * 16u, wsrc + (size_t)i * 16);
        }
    };

    // L0 X staging: LDG.128 -> RNA round -> permuted scatter STS.32 (stride 20, conflict-free)
    auto ldg_x = [&](int c) {
        float4 v = *(const float4*)(xg + (size_t)xrow * 98304 + c * 16 + xblk * 4);
        v.x = tf32rf(v.x); v.y = tf32rf(v.y); v.z = tf32rf(v.z); v.w = tf32rf(v.w);
        return v;
    };
    auto sts_x = [&](int c, float4 v) {
        // thread holds k = 4*xblk + j (j=0..3); store at perm position 4*j + xblk
        float* d = Xc + (c & 3) * 2560 + xrow * 20 + xblk;
        d[0] = v.x; d[4] = v.y; d[8] = v.z; d[12] = v.w;
    };

    const int q = lane & 3, g4 = lane >> 2;

    // A-fragment loader for chunk c: uniform 4x LDS.128 (both layers, permuted layouts)
    auto load_frags = [&](int c, float4 a0[2], float4 a1[2]) {
        if (IS_L0) {
            const float* Xs = Xc + (c & 3) * 2560;
#pragma unroll
            for (int f = 0; f < 2; f++) {
                const float* p0 = Xs + (m_idx * 32 + f * 16 + g4) * 20 + 4 * q;
                a0[f] = *(const float4*)p0;
                a1[f] = *(const float4*)(p0 + 8 * 20);
            }
        } else {
            const int colb = c * 16 + 4 * q;
#pragma unroll
            for (int f = 0; f < 2; f++) {
                const float* p0 = Ys + (m_idx * 32 + f * 16 + g4) * LDY + colb;
                a0[f] = *(const float4*)p0;
                a1[f] = *(const float4*)(p0 + 8 * LDY);
            }
        }
    };

    // depth-3 W prologue + X slots 0,1 staged, chunk-2 X held in registers
    stageW(0); CP_COMMIT();
    stageW(1); CP_COMMIT();
    stageW(2); CP_COMMIT();
    float4 xr = {0.f, 0.f, 0.f, 0.f};
    if (IS_L0) {
        sts_x(0, ldg_x(0));
        sts_x(1, ldg_x(1));
        xr = ldg_x(2);
    }

    float4 a0[2], a1[2];
    CP_WAIT2();                 // W chunk 0 landed
    __syncthreads();            // publish W0 + X slots 0,1
    load_frags(0, a0, a1);

#pragma unroll 4
    for (int c = 0; c < NC; c++) {
        // ---- prefetch chunk c+1's A fragments (overlaps chunk c's MMAs) ----
        float4 na0[2], na1[2];
        if (c + 1 < NC) {
            CP_WAIT1();         // W chunks 0..c+1 landed (c+2 may be pending)
            __syncthreads();    // publish W c+1 and X slot c+1 (STS'd last iteration)
            load_frags(c + 1, na0, na1);
        }

        // ---- MMA over N tiles for chunk c ----
        const float* Ws = WcF + (c & 3) * 4096;
#pragma unroll
        for (int t = 0; t < NT; t++) {
            const int nb = n_idx * (N / 4) + t * 8 + g4;
            float4 bv = *(const float4*)(Ws + nb * 16 + 4 * q);
#pragma unroll
            for (int f = 0; f < 2; f++) {
                mma_tf32(acc[f][t],
                         __float_as_uint(a0[f].x), __float_as_uint(a1[f].x),
                         __float_as_uint(a0[f].y), __float_as_uint(a1[f].y),
                         __float_as_uint(bv.x), __float_as_uint(bv.y));
                mma_tf32(acc[f][t],
                         __float_as_uint(a0[f].z), __float_as_uint(a1[f].z),
                         __float_as_uint(a0[f].w), __float_as_uint(a1[f].w),
                         __float_as_uint(bv.z), __float_as_uint(bv.w));
            }
        }

        if (c + 3 < NC) stageW(c + 3);
        CP_COMMIT();            // unconditional: keeps wait_group accounting exact

        if (IS_L0) {
            if (c + 2 < NC) sts_x(c + 2, xr);     // slot (c+2)&3 = chunk c-2's (reads long done)
            if (c + 3 < NC) xr = ldg_x(c + 3);    // held across next MMA chunk
        }

        if (c + 1 < NC) {
            a0[0] = na0[0]; a0[1] = na0[1];
            a1[0] = na1[0]; a1[1] = na1[1];
        }
    }
    __syncthreads();   // all MMA/B/X reads done before epilogue overwrites Ys

    // ---- epilogue: +bias, celu, (round), permuted store to Ys ----
#pragma unroll
    for (int f = 0; f < 2; f++) {
#pragma unroll
        for (int t = 0; t < NT; t++) {
            const int r = m_idx * 32 + f * 16 + g4;
            const int cn = n_idx * (N / 4) + t * 8 + 2 * q;
            const float bv0 = __ldg(bg + cn), bv1 = __ldg(bg + cn + 1);
            float v0 = celu_f(acc[f][t][0] + bv0);
            float v1 = celu_f(acc[f][t][1] + bv1);
            float v2 = celu_f(acc[f][t][2] + bv0);
            float v3 = celu_f(acc[f][t][3] + bv1);
            if (ROUND) {
                v0 = tf32rf(v0); v1 = tf32rf(v1);
                v2 = tf32rf(v2); v3 = tf32rf(v3);
            }
            const int w0 = cn & 15, w1 = (cn + 1) & 15;
            const int p0 = (cn & ~15) + (((w0 & 3) << 2) | (w0 >> 2));
            const int p1 = (cn & ~15) + (((w1 & 3) << 2) | (w1 >> 2));
            Ys[r * LDY + p0] = v0;
            Ys[r * LDY + p1] = v1;
            Ys[(r + 8) * LDY + p0] = v2;
            Ys[(r + 8) * LDY + p1] = v3;
        }
    }
    __syncthreads();
}

// ---------------- fused kernel ----------------
__global__ void __launch_bounds__(512, 1)
aev_mlp_mma(const float* __restrict__ fullaev, const int* __restrict__ species,
            const float* __restrict__ b0, const float* __restrict__ b1,
            const float* __restrict__ b2,
            const float* __restrict__ W3, const float* __restrict__ b3)
{
    extern __shared__ float sm[];
    float* Ys = sm;
    const float* WcF = sm + OFF_W;
    float* Xc = sm;                         // X ring overlays Ys during L0
    const uint32_t smU = smem_u32(sm);
    const uint32_t wcU = smU + OFF_W * 4;

    const int a = blockIdx.y;
    const int bbase = blockIdx.x * 128;
    const int tid = threadIdx.x;
    const int lane = tid & 31, wid = tid >> 5;
    const int m_idx = wid >> 2, n_idx = wid & 3;
    const int s = species[a];
    const float* xg = fullaev + (size_t)bbase * 98304 + (size_t)a * 384;

    layer_run<384, 256, true,  true >(g_Wp0 + (size_t)s * (24 * 256 * 16), b0 + s * 256, xg,
                                      Ys, WcF, Xc, wcU, tid, lane, m_idx, n_idx);
    layer_run<256, 192, false, true >(g_Wp1 + (size_t)s * (16 * 192 * 16), b1 + s * 192, xg,
                                      Ys, WcF, Xc, wcU, tid, lane, m_idx, n_idx);
    layer_run<192, 160, false, false>(g_Wp2 + (size_t)s * (12 * 160 * 16), b2 + s * 160, xg,
                                      Ys, WcF, Xc, wcU, tid, lane, m_idx, n_idx);

    // ---- layer 3: dot(Y2[r, 0:160], w3) + b3, celu ----
    if (tid < 128) {
        const float* w = W3 + s * 160;
        float s0 = 0.f, s1 = 0.f, s2 = 0.f, s3 = 0.f;
        const float* yr = Ys + tid * LDY;
#pragma unroll
        for (int k = 0; k < 160; k += 4) {
            const int gb = k & ~15;
            const int w0 = k & 15;
            const int pA = gb + (((w0 & 3) << 2) | (w0 >> 2));
            const int w1 = (k + 1) & 15, w2 = (k + 2) & 15, w3i = (k + 3) & 15;
            const int pB = gb + (((w1 & 3) << 2) | (w1 >> 2));
            const int pC = gb + (((w2 & 3) << 2) | (w2 >> 2));
            const int pD = gb + (((w3i & 3) << 2) | (w3i >> 2));
            s0 = fmaf(yr[pA], __ldg(w + k + 0), s0);
            s1 = fmaf(yr[pB], __ldg(w + k + 1), s1);
            s2 = fmaf(yr[pC], __ldg(w + k + 2), s2);
            s3 = fmaf(yr[pD], __ldg(w + k + 3), s3);
        }
        float acc = ((s0 + s1) + (s2 + s3)) + __ldg(b3 + s);
        g_partial[(size_t)a * 1024 + bbase + tid] = celu_f(acc);
    }
}

// ---------------- deterministic two-stage reduction ----------------
__global__ void reduce1() {
    int b = blockIdx.x * 256 + threadIdx.x;
    int ag = blockIdx.y;
    float acc = 0.f;
#pragma unroll
    for (int i = 0; i < 32; i++) acc += g_partial[(size_t)(ag * 32 + i) * 1024 + b];
    g_red[ag * 1024 + b] = acc;
}
__global__ void reduce2(float* __restrict__ out) {
    int b = blockIdx.x * 256 + threadIdx.x;
    float acc = 0.f;
#pragma unroll
    for (int g = 0; g < 8; g++) acc += g_red[g * 1024 + b];
    out[b] = acc;
}

extern "C" void kernel_launch(void* const* d_in, const int* in_sizes, int n_in,
                              void* d_out, int out_size) {
    const float* fullaev = (const float*)d_in[0];
    const int*   species = (const int*)d_in[1];
    const float* W0 = (const float*)d_in[2];
    const float* b0 = (const float*)d_in[3];
    const float* W1 = (const float*)d_in[4];
    const float* b1 = (const float*)d_in[5];
    const float* W2 = (const float*)d_in[6];
    const float* b2 = (const float*)d_in[7];
    const float* W3 = (const float*)d_in[8];
    const float* b3 = (const float*)d_in[9];

    prep_w<384, 256, 0><<<(4 * 384 * 256 + 255) / 256, 256>>>(W0);
    prep_w<256, 192, 1><<<(4 * 256 * 192 + 255) / 256, 256>>>(W1);
    prep_w<192, 160, 2><<<(4 * 192 * 160 + 255) / 256, 256>>>(W2);

    cudaFuncSetAttribute(aev_mlp_mma, cudaFuncAttributeMaxDynamicSharedMemorySize, SMEM_BYTES);
    dim3 grid(8, 256);   // (B-tiles of 128, atoms)
    aev_mlp_mma<<<grid, 512, SMEM_BYTES>>>(fullaev, species, b0, b1, b2, W3, b3);

    reduce1<<<dim3(4, 8), 256>>>();
    reduce2<<<4, 256>>>((float*)d_out);
}

// round 13
// speedup vs baseline: 1.2774x; 1.2774x over previous
#include <cuda_runtime.h>
#include <cstdint>
#include <math.h>

#define ALPHA_CELU 0.1f

// ---------------- device scratch ----------------
__device__ float g_Wp0[4 * 24 * 256 * 16];   // [s][chunk][n][16 perm k]  (tf32-rounded)
__device__ float g_Wp1[4 * 16 * 192 * 16];
__device__ float g_Wp2[4 * 12 * 160 * 16];
__device__ float g_partial[256 * 1024];      // [atom][b]
__device__ float g_red[8 * 1024];

// ---------------- helpers ----------------
// Branchless CELU: max(x,0) + min(0, alpha*(exp(x/alpha)-1)).
__device__ __forceinline__ float celu_f(float x) {
    float e = __expf(x * (1.f / ALPHA_CELU));
    return fmaxf(x, 0.f) + fminf(0.f, ALPHA_CELU * (e - 1.f));
}
__device__ __forceinline__ uint32_t tf32r(float x) {   // RNA round to tf32
    uint32_t u;
    asm("cvt.rna.tf32.f32 %0, %1;" : "=r"(u) : "f"(x));
    return u;
}
__device__ __forceinline__ float tf32rf(float x) { return __uint_as_float(tf32r(x)); }
__device__ __forceinline__ uint32_t smem_u32(const void* p) {
    uint32_t a;
    asm("{ .reg .u64 t; cvta.to.shared.u64 t, %1; cvt.u32.u64 %0, t; }" : "=r"(a) : "l"(p));
    return a;
}
__device__ __forceinline__ void mma_tf32(float c[4],
                                         uint32_t a0, uint32_t a1, uint32_t a2, uint32_t a3,
                                         uint32_t b0, uint32_t b1) {
    asm volatile("mma.sync.aligned.m16n8k8.row.col.f32.tf32.tf32.f32 "
                 "{%0,%1,%2,%3}, {%4,%5,%6,%7}, {%8,%9}, {%0,%1,%2,%3};"
                 : "+f"(c[0]), "+f"(c[1]), "+f"(c[2]), "+f"(c[3])
                 : "r"(a0), "r"(a1), "r"(a2), "r"(a3), "r"(b0), "r"(b1));
}
#define CP_ASYNC16(dst, src) \
    asm volatile("cp.async.ca.shared.global [%0], [%1], 16;" :: "r"(dst), "l"(src))
#define CP_COMMIT() asm volatile("cp.async.commit_group;" ::: "memory")
#define CP_WAIT1()  asm volatile("cp.async.wait_group 1;" ::: "memory")
#define CP_WAIT2()  asm volatile("cp.async.wait_group 2;" ::: "memory")

// ---------------- smem layout (floats) ----------------
// Ys: 128 x 272 only.  X ring (L0, 4 slots x 2560 floats, stride 20, raw fp32)
// OVERLAYS Ys rows 0..37.  No W smem at all (B frags come from L2/L1 via __ldg).
#define LDY 272
#define SMEM_FLOATS (128 * LDY)           // 34816 floats
#define SMEM_BYTES (SMEM_FLOATS * 4)      // 139264 B

// ---------------- weight prep: [S,K,N] -> [s][k/16][n][perm(k&15)] tf32 ----------------
template<int K, int N, int WHICH>
__global__ void prep_w(const float* __restrict__ W) {
    int i = blockIdx.x * blockDim.x + threadIdx.x;
    if (i >= 4 * K * N) return;
    float* dst = (WHICH == 0) ? g_Wp0 : (WHICH == 1) ? g_Wp1 : g_Wp2;
    int n = i % N, k = (i / N) % K, s = i / (N * K);
    int chunk = k >> 4, w = k & 15;
    int p = ((w & 3) << 2) | (w >> 2);
    dst[((size_t)(s * (K / 16) + chunk) * N + n) * 16 + p] = __uint_as_float(tf32r(W[i]));
}

// ---------------- one layer (512 threads, warp grid 4m x 4n, warp tile 32 x N/4) ----------------
template<int K, int N, bool IS_L0, bool ROUND>
__device__ __forceinline__ void layer_run(
    const float* __restrict__ Wp, const float* __restrict__ bg,
    const float* __restrict__ xg,
    float* __restrict__ Ys, const float* __restrict__ XcF, uint32_t xcU,
    int tid, int lane, int m_idx, int n_idx)
{
    constexpr int NT = N / 32;                // n8 tiles per warp (8 / 6 / 5)
    constexpr int NC = K / 16;

    float acc[2][NT][4];
#pragma unroll
    for (int f = 0; f < 2; f++)
#pragma unroll
        for (int t = 0; t < NT; t++)
#pragma unroll
            for (int j = 0; j < 4; j++) acc[f][t][j] = 0.f;

    const int xrow = tid >> 2, xblk = tid & 3;   // 512 thr = 128 rows x 4 k-quads

    // L0-only: X staging via cp.async into 4-slot ring (raw fp32, linear k)
    auto stageX = [&](int c) {
        const uint32_t xdst = xcU + (uint32_t)(c & 3) * 10240u;
        const float* src = xg + (size_t)xrow * 98304 + c * 16 + xblk * 4;
        CP_ASYNC16(xdst + (uint32_t)(xrow * 80 + xblk * 16), src);
    };

    const int q = lane & 3, g4 = lane >> 2;

    // A-fragment loader for chunk c (into caller registers)
    auto load_frags = [&](int c, float4 a0[2], float4 a1[2]) {
        if (IS_L0) {
            const float* Xs = XcF + (c & 3) * 2560;
#pragma unroll
            for (int f = 0; f < 2; f++) {
                const float* p0 = Xs + (m_idx * 32 + f * 16 + g4) * 20 + q;
                const float* p1 = p0 + 8 * 20;
                a0[f].x = tf32rf(p0[0]);  a0[f].y = tf32rf(p0[4]);
                a0[f].z = tf32rf(p0[8]);  a0[f].w = tf32rf(p0[12]);
                a1[f].x = tf32rf(p1[0]);  a1[f].y = tf32rf(p1[4]);
                a1[f].z = tf32rf(p1[8]);  a1[f].w = tf32rf(p1[12]);
            }
        } else {
            const int colb = c * 16 + 4 * q;
#pragma unroll
            for (int f = 0; f < 2; f++) {
                const float* p0 = Ys + (m_idx * 32 + f * 16 + g4) * LDY + colb;
                a0[f] = *(const float4*)p0;
                a1[f] = *(const float4*)(p0 + 8 * LDY);
            }
        }
    };

    if (IS_L0) {
        stageX(0); CP_COMMIT();
        stageX(1); CP_COMMIT();
        stageX(2); CP_COMMIT();
        CP_WAIT2();             // X chunk 0 landed
        __syncthreads();        // publish X slot 0
    }

    float4 a0[2], a1[2];
    load_frags(0, a0, a1);

#pragma unroll 4
    for (int c = 0; c < NC; c++) {
        // ---- prefetch chunk c+1's A fragments (overlaps chunk c's MMAs) ----
        float4 na0[2], na1[2];
        if (c + 1 < NC) {
            if (IS_L0) {
                CP_WAIT1();     // X chunks 0..c+1 landed (c+2 may be pending)
                __syncthreads();
            }
            load_frags(c + 1, na0, na1);
        }

        // ---- MMA over N tiles for chunk c; B fragments direct from L2/L1 ----
        const float* Wb = Wp + (size_t)c * (N * 16);
#pragma unroll
        for (int t = 0; t < NT; t++) {
            const int nb = n_idx * (N / 4) + t * 8 + g4;
            float4 bv = __ldg((const float4*)(Wb + nb * 16 + 4 * q));
#pragma unroll
            for (int f = 0; f < 2; f++) {
                mma_tf32(acc[f][t],
                         __float_as_uint(a0[f].x), __float_as_uint(a1[f].x),
                         __float_as_uint(a0[f].y), __float_as_uint(a1[f].y),
                         __float_as_uint(bv.x), __float_as_uint(bv.y));
                mma_tf32(acc[f][t],
                         __float_as_uint(a0[f].z), __float_as_uint(a1[f].z),
                         __float_as_uint(a0[f].w), __float_as_uint(a1[f].w),
                         __float_as_uint(bv.z), __float_as_uint(bv.w));
            }
        }

        if (IS_L0) {
            if (c + 3 < NC) stageX(c + 3);
            CP_COMMIT();        // unconditional: keeps wait_group accounting exact
        }

        if (c + 1 < NC) {
            a0[0] = na0[0]; a0[1] = na0[1];
            a1[0] = na1[0]; a1[1] = na1[1];
        }
    }
    __syncthreads();   // all MMA/X reads done before epilogue overwrites Ys

    // ---- epilogue: +bias, celu, (round), permuted store to Ys ----
#pragma unroll
    for (int f = 0; f < 2; f++) {
#pragma unroll
        for (int t = 0; t < NT; t++) {
            const int r = m_idx * 32 + f * 16 + g4;
            const int cn = n_idx * (N / 4) + t * 8 + 2 * q;
            const float bv0 = __ldg(bg + cn), bv1 = __ldg(bg + cn + 1);
            float v0 = celu_f(acc[f][t][0] + bv0);
            float v1 = celu_f(acc[f][t][1] + bv1);
            float v2 = celu_f(acc[f][t][2] + bv0);
            float v3 = celu_f(acc[f][t][3] + bv1);
            if (ROUND) {
                v0 = tf32rf(v0); v1 = tf32rf(v1);
                v2 = tf32rf(v2); v3 = tf32rf(v3);
            }
            const int w0 = cn & 15, w1 = (cn + 1) & 15;
            const int p0 = (cn & ~15) + (((w0 & 3) << 2) | (w0 >> 2));
            const int p1 = (cn & ~15) + (((w1 & 3) << 2) | (w1 >> 2));
            Ys[r * LDY + p0] = v0;
            Ys[r * LDY + p1] = v1;
            Ys[(r + 8) * LDY + p0] = v2;
            Ys[(r + 8) * LDY + p1] = v3;
        }
    }
    __syncthreads();
}

// ---------------- fused kernel ----------------
__global__ void __launch_bounds__(512, 1)
aev_mlp_mma(const float* __restrict__ fullaev, const int* __restrict__ species,
            const float* __restrict__ b0, const float* __restrict__ b1,
            const float* __restrict__ b2,
            const float* __restrict__ W3, const float* __restrict__ b3)
{
    extern __shared__ float sm[];
    float* Ys = sm;
    const float* XcF = sm;                  // X ring overlays Ys during L0
    const uint32_t xcU = smem_u32(sm);

    const int a = blockIdx.y;
    const int bbase = blockIdx.x * 128;
    const int tid = threadIdx.x;
    const int lane = tid & 31, wid = tid >> 5;
    const int m_idx = wid >> 2, n_idx = wid & 3;
    const int s = species[a];
    const float* xg = fullaev + (size_t)bbase * 98304 + (size_t)a * 384;

    layer_run<384, 256, true,  true >(g_Wp0 + (size_t)s * (24 * 256 * 16), b0 + s * 256, xg,
                                      Ys, XcF, xcU, tid, lane, m_idx, n_idx);
    layer_run<256, 192, false, true >(g_Wp1 + (size_t)s * (16 * 192 * 16), b1 + s * 192, xg,
                                      Ys, XcF, xcU, tid, lane, m_idx, n_idx);
    layer_run<192, 160, false, false>(g_Wp2 + (size_t)s * (12 * 160 * 16), b2 + s * 160, xg,
                                      Ys, XcF, xcU, tid, lane, m_idx, n_idx);

    // ---- layer 3: dot(Y2[r, 0:160], w3) + b3, celu ----
    if (tid < 128) {
        const float* w = W3 + s * 160;
        float s0 = 0.f, s1 = 0.f, s2 = 0.f, s3 = 0.f;
        const float* yr = Ys + tid * LDY;
#pragma unroll
        for (int k = 0; k < 160; k += 4) {
            const int gb = k & ~15;
            const int w0 = k & 15;
            const int pA = gb + (((w0 & 3) << 2) | (w0 >> 2));
            const int w1 = (k + 1) & 15, w2 = (k + 2) & 15, w3i = (k + 3) & 15;
            const int pB = gb + (((w1 & 3) << 2) | (w1 >> 2));
            const int pC = gb + (((w2 & 3) << 2) | (w2 >> 2));
            const int pD = gb + (((w3i & 3) << 2) | (w3i >> 2));
            s0 = fmaf(yr[pA], __ldg(w + k + 0), s0);
            s1 = fmaf(yr[pB], __ldg(w + k + 1), s1);
            s2 = fmaf(yr[pC], __ldg(w + k + 2), s2);
            s3 = fmaf(yr[pD], __ldg(w + k + 3), s3);
        }
        float acc = ((s0 + s1) + (s2 + s3)) + __ldg(b3 + s);
        g_partial[(size_t)a * 1024 + bbase + tid] = celu_f(acc);
    }
}

// ---------------- deterministic two-stage reduction ----------------
__global__ void reduce1() {
    int b = blockIdx.x * 256 + threadIdx.x;
    int ag = blockIdx.y;
    float acc = 0.f;
#pragma unroll
    for (int i = 0; i < 32; i++) acc += g_partial[(size_t)(ag * 32 + i) * 1024 + b];
    g_red[ag * 1024 + b] = acc;
}
__global__ void reduce2(float* __restrict__ out) {
    int b = blockIdx.x * 256 + threadIdx.x;
    float acc = 0.f;
#pragma unroll
    for (int g = 0; g < 8; g++) acc += g_red[g * 1024 + b];
    out[b] = acc;
}

extern "C" void kernel_launch(void* const* d_in, const int* in_sizes, int n_in,
                              void* d_out, int out_size) {
    const float* fullaev = (const float*)d_in[0];
    const int*   species = (const int*)d_in[1];
    const float* W0 = (const float*)d_in[2];
    const float* b0 = (const float*)d_in[3];
    const float* W1 = (const float*)d_in[4];
    const float* b1 = (const float*)d_in[5];
    const float* W2 = (const float*)d_in[6];
    const float* b2 = (const float*)d_in[7];
    const float* W3 = (const float*)d_in[8];
    const float* b3 = (const float*)d_in[9];

    prep_w<384, 256, 0><<<(4 * 384 * 256 + 255) / 256, 256>>>(W0);
    prep_w<256, 192, 1><<<(4 * 256 * 192 + 255) / 256, 256>>>(W1);
    prep_w<192, 160, 2><<<(4 * 192 * 160 + 255) / 256, 256>>>(W2);

    cudaFuncSetAttribute(aev_mlp_mma, cudaFuncAttributeMaxDynamicSharedMemorySize, SMEM_BYTES);
    dim3 grid(8, 256);   // (B-tiles of 128, atoms)
    aev_mlp_mma<<<grid, 512, SMEM_BYTES>>>(fullaev, species, b0, b1, b2, W3, b3);

    reduce1<<<dim3(4, 8), 256>>>();
    reduce2<<<4, 256>>>((float*)d_out);
}

// round 14
// speedup vs baseline: 1.4114x; 1.1049x over previous
#include <cuda_runtime.h>
#include <cstdint>
#include <math.h>

#define ALPHA_CELU 0.1f

// ---------------- device scratch ----------------
__device__ float g_Wp0[4 * 24 * 256 * 16];   // [s][chunk][n][16 perm k]  (tf32-rounded)
__device__ float g_Wp1[4 * 16 * 192 * 16];
__device__ float g_Wp2[4 * 12 * 160 * 16];
__device__ float g_partial[256 * 1024];      // [atom][b]
__device__ float g_red[8 * 1024];

// ---------------- helpers ----------------
// Branchless CELU: max(x,0) + min(0, alpha*(exp(x/alpha)-1)).
__device__ __forceinline__ float celu_f(float x) {
    float e = __expf(x * (1.f / ALPHA_CELU));
    return fmaxf(x, 0.f) + fminf(0.f, ALPHA_CELU * (e - 1.f));
}
__device__ __forceinline__ uint32_t tf32r(float x) {   // RNA round to tf32
    uint32_t u;
    asm("cvt.rna.tf32.f32 %0, %1;" : "=r"(u) : "f"(x));
    return u;
}
__device__ __forceinline__ float tf32rf(float x) { return __uint_as_float(tf32r(x)); }
__device__ __forceinline__ uint32_t smem_u32(const void* p) {
    uint32_t a;
    asm("{ .reg .u64 t; cvta.to.shared.u64 t, %1; cvt.u32.u64 %0, t; }" : "=r"(a) : "l"(p));
    return a;
}
__device__ __forceinline__ void mma_tf32(float c[4],
                                         uint32_t a0, uint32_t a1, uint32_t a2, uint32_t a3,
                                         uint32_t b0, uint32_t b1) {
    asm volatile("mma.sync.aligned.m16n8k8.row.col.f32.tf32.tf32.f32 "
                 "{%0,%1,%2,%3}, {%4,%5,%6,%7}, {%8,%9}, {%0,%1,%2,%3};"
                 : "+f"(c[0]), "+f"(c[1]), "+f"(c[2]), "+f"(c[3])
                 : "r"(a0), "r"(a1), "r"(a2), "r"(a3), "r"(b0), "r"(b1));
}
#define CP_ASYNC16(dst, src) \
    asm volatile("cp.async.ca.shared.global [%0], [%1], 16;" :: "r"(dst), "l"(src))
#define CP_COMMIT() asm volatile("cp.async.commit_group;" ::: "memory")
#define CP_WAIT1()  asm volatile("cp.async.wait_group 1;" ::: "memory")

// ---------------- smem layout (floats) ----------------
// Ys: 128 x 272 only (139264 B).  X ring (L0): 3 GROUPS x 4 chunks x 2560 floats
// = 30720 floats (122880 B), OVERLAYS Ys rows 0..112.  No W smem (B via __ldg).
#define LDY 272
#define SMEM_FLOATS (128 * LDY)           // 34816 floats
#define SMEM_BYTES (SMEM_FLOATS * 4)      // 139264 B

// ---------------- weight prep: [S,K,N] -> [s][k/16][n][perm(k&15)] tf32 ----------------
template<int K, int N, int WHICH>
__global__ void prep_w(const float* __restrict__ W) {
    int i = blockIdx.x * blockDim.x + threadIdx.x;
    if (i >= 4 * K * N) return;
    float* dst = (WHICH == 0) ? g_Wp0 : (WHICH == 1) ? g_Wp1 : g_Wp2;
    int n = i % N, k = (i / N) % K, s = i / (N * K);
    int chunk = k >> 4, w = k & 15;
    int p = ((w & 3) << 2) | (w >> 2);
    dst[((size_t)(s * (K / 16) + chunk) * N + n) * 16 + p] = __uint_as_float(tf32r(W[i]));
}

// ---------------- shared epilogue: +bias, celu, (round), permuted store to Ys ----------
template<int N, bool ROUND, int NT>
__device__ __forceinline__ void epilogue_store(
    float acc[2][NT][4], const float* __restrict__ bg, float* __restrict__ Ys,
    int m_idx, int n_idx, int q, int g4)
{
#pragma unroll
    for (int f = 0; f < 2; f++) {
#pragma unroll
        for (int t = 0; t < NT; t++) {
            const int r = m_idx * 32 + f * 16 + g4;
            const int cn = n_idx * (N / 4) + t * 8 + 2 * q;
            const float bv0 = __ldg(bg + cn), bv1 = __ldg(bg + cn + 1);
            float v0 = celu_f(acc[f][t][0] + bv0);
            float v1 = celu_f(acc[f][t][1] + bv1);
            float v2 = celu_f(acc[f][t][2] + bv0);
            float v3 = celu_f(acc[f][t][3] + bv1);
            if (ROUND) {
                v0 = tf32rf(v0); v1 = tf32rf(v1);
                v2 = tf32rf(v2); v3 = tf32rf(v3);
            }
            const int w0 = cn & 15, w1 = (cn + 1) & 15;
            const int p0 = (cn & ~15) + (((w0 & 3) << 2) | (w0 >> 2));
            const int p1 = (cn & ~15) + (((w1 & 3) << 2) | (w1 >> 2));
            Ys[r * LDY + p0] = v0;
            Ys[r * LDY + p1] = v1;
            Ys[(r + 8) * LDY + p0] = v2;
            Ys[(r + 8) * LDY + p1] = v3;
        }
    }
}

// ---------------- MMA for one chunk (B fragments direct from L2/L1) ----------------
template<int N, int NT>
__device__ __forceinline__ void mma_chunk(
    float acc[2][NT][4], const float* __restrict__ Wb,
    const float4 a0[2], const float4 a1[2], int n_idx, int q, int g4)
{
#pragma unroll
    for (int t = 0; t < NT; t++) {
        const int nb = n_idx * (N / 4) + t * 8 + g4;
        float4 bv = __ldg((const float4*)(Wb + nb * 16 + 4 * q));
#pragma unroll
        for (int f = 0; f < 2; f++) {
            mma_tf32(acc[f][t],
                     __float_as_uint(a0[f].x), __float_as_uint(a1[f].x),
                     __float_as_uint(a0[f].y), __float_as_uint(a1[f].y),
                     __float_as_uint(bv.x), __float_as_uint(bv.y));
            mma_tf32(acc[f][t],
                     __float_as_uint(a0[f].z), __float_as_uint(a1[f].z),
                     __float_as_uint(a0[f].w), __float_as_uint(a1[f].w),
                     __float_as_uint(bv.z), __float_as_uint(bv.w));
        }
    }
}

// ---------------- layer 0: X streamed in GROUPS of 4 chunks, 3-group ring ----------
__device__ __forceinline__ void layer0_run(
    const float* __restrict__ Wp, const float* __restrict__ bg,
    const float* __restrict__ xg,
    float* __restrict__ Ys, const float* __restrict__ XcF, uint32_t xcU,
    int tid, int lane, int m_idx, int n_idx)
{
    constexpr int NT = 8, NG = 6;             // N=256, K=384: 24 chunks = 6 groups of 4

    float acc[2][NT][4];
#pragma unroll
    for (int f = 0; f < 2; f++)
#pragma unroll
        for (int t = 0; t < NT; t++)
#pragma unroll
            for (int j = 0; j < 4; j++) acc[f][t][j] = 0.f;

    const int xrow = tid >> 2, xblk = tid & 3;   // 512 thr = 128 rows x 4 k-quads
    const int q = lane & 3, g4 = lane >> 2;

    auto stageX = [&](int c) {   // chunk c -> group slot (c/4)%3, sub-slot c%4
        const uint32_t xdst = xcU + (uint32_t)((c >> 2) % 3) * 40960u
                                  + (uint32_t)(c & 3) * 10240u;
        const float* src = xg + (size_t)xrow * 98304 + c * 16 + xblk * 4;
        CP_ASYNC16(xdst + (uint32_t)(xrow * 80 + xblk * 16), src);
    };
    auto load_frags = [&](int c, float4 a0[2], float4 a1[2]) {
        const float* Xs = XcF + ((c >> 2) % 3) * 10240 + (c & 3) * 2560;
#pragma unroll
        for (int f = 0; f < 2; f++) {
            const float* p0 = Xs + (m_idx * 32 + f * 16 + g4) * 20 + q;
            const float* p1 = p0 + 8 * 20;
            a0[f].x = tf32rf(p0[0]);  a0[f].y = tf32rf(p0[4]);
            a0[f].z = tf32rf(p0[8]);  a0[f].w = tf32rf(p0[12]);
            a1[f].x = tf32rf(p1[0]);  a1[f].y = tf32rf(p1[4]);
            a1[f].z = tf32rf(p1[8]);  a1[f].w = tf32rf(p1[12]);
        }
    };

    // prologue: groups 0 and 1 in flight
#pragma unroll
    for (int j = 0; j < 4; j++) stageX(j);
    CP_COMMIT();
#pragma unroll
    for (int j = 4; j < 8; j++) stageX(j);
    CP_COMMIT();

#pragma unroll
    for (int g = 0; g < NG; g++) {
        CP_WAIT1();                 // group g landed (only group g+1 may be pending)
        __syncthreads();            // publish group g; all reads of group g-1 complete

        if (g + 2 < NG) {           // stage group g+2 into slot (g+2)%3 = (g-1)%3
#pragma unroll
            for (int j = 0; j < 4; j++) stageX(4 * (g + 2) + j);
        }
        CP_COMMIT();                // unconditional: keeps wait accounting exact

        // 4 chunks, barrier-free, with A-fragment register prefetch
        float4 a0[2], a1[2];
        load_frags(4 * g, a0, a1);
#pragma unroll
        for (int j = 0; j < 4; j++) {
            const int c = 4 * g + j;
            float4 na0[2], na1[2];
            if (j < 3) load_frags(c + 1, na0, na1);
            mma_chunk<256, NT>(acc, Wp + (size_t)c * 4096, a0, a1, n_idx, q, g4);
            if (j < 3) {
                a0[0] = na0[0]; a0[1] = na0[1];
                a1[0] = na1[0]; a1[1] = na1[1];
            }
        }
    }
    __syncthreads();   // all X reads done before epilogue overwrites Ys

    epilogue_store<256, true, NT>(acc, bg, Ys, m_idx, n_idx, q, g4);
    __syncthreads();
}

// ---------------- layers 1/2: A resident in Ys, fully barrier-free mainloop --------
template<int K, int N, bool ROUND>
__device__ __forceinline__ void layerR_run(
    const float* __restrict__ Wp, const float* __restrict__ bg,
    float* __restrict__ Ys,
    int lane, int m_idx, int n_idx)
{
    constexpr int NT = N / 32;
    constexpr int NC = K / 16;

    float acc[2][NT][4];
#pragma unroll
    for (int f = 0; f < 2; f++)
#pragma unroll
        for (int t = 0; t < NT; t++)
#pragma unroll
            for (int j = 0; j < 4; j++) acc[f][t][j] = 0.f;

    const int q = lane & 3, g4 = lane >> 2;

    auto load_frags = [&](int c, float4 a0[2], float4 a1[2]) {
        const int colb = c * 16 + 4 * q;
#pragma unroll
        for (int f = 0; f < 2; f++) {
            const float* p0 = Ys + (m_idx * 32 + f * 16 + g4) * LDY + colb;
            a0[f] = *(const float4*)p0;
            a1[f] = *(const float4*)(p0 + 8 * LDY);
        }
    };

    float4 a0[2], a1[2];
    load_frags(0, a0, a1);

#pragma unroll 4
    for (int c = 0; c < NC; c++) {
        float4 na0[2], na1[2];
        if (c + 1 < NC) load_frags(c + 1, na0, na1);
        mma_chunk<N, NT>(acc, Wp + (size_t)c * (N * 16), a0, a1, n_idx, q, g4);
        if (c + 1 < NC) {
            a0[0] = na0[0]; a0[1] = na0[1];
            a1[0] = na1[0]; a1[1] = na1[1];
        }
    }
    __syncthreads();   // all Ys reads done before epilogue overwrites Ys

    epilogue_store<N, ROUND, NT>(acc, bg, Ys, m_idx, n_idx, q, g4);
    __syncthreads();
}

// ---------------- fused kernel ----------------
__global__ void __launch_bounds__(512, 1)
aev_mlp_mma(const float* __restrict__ fullaev, const int* __restrict__ species,
            const float* __restrict__ b0, const float* __restrict__ b1,
            const float* __restrict__ b2,
            const float* __restrict__ W3, const float* __restrict__ b3)
{
    extern __shared__ float sm[];
    float* Ys = sm;
    const float* XcF = sm;                  // X ring overlays Ys during L0
    const uint32_t xcU = smem_u32(sm);

    const int a = blockIdx.y;
    const int bbase = blockIdx.x * 128;
    const int tid = threadIdx.x;
    const int lane = tid & 31, wid = tid >> 5;
    const int m_idx = wid >> 2, n_idx = wid & 3;
    const int s = species[a];
    const float* xg = fullaev + (size_t)bbase * 98304 + (size_t)a * 384;

    layer0_run(g_Wp0 + (size_t)s * (24 * 256 * 16), b0 + s * 256, xg,
               Ys, XcF, xcU, tid, lane, m_idx, n_idx);
    layerR_run<256, 192, true >(g_Wp1 + (size_t)s * (16 * 192 * 16), b1 + s * 192,
                                Ys, lane, m_idx, n_idx);
    layerR_run<192, 160, false>(g_Wp2 + (size_t)s * (12 * 160 * 16), b2 + s * 160,
                                Ys, lane, m_idx, n_idx);

    // ---- layer 3: dot(Y2[r, 0:160], w3) + b3, celu ----
    if (tid < 128) {
        const float* w = W3 + s * 160;
        float s0 = 0.f, s1 = 0.f, s2 = 0.f, s3 = 0.f;
        const float* yr = Ys + tid * LDY;
#pragma unroll
        for (int k = 0; k < 160; k += 4) {
            const int gb = k & ~15;
            const int w0 = k & 15;
            const int pA = gb + (((w0 & 3) << 2) | (w0 >> 2));
            const int w1 = (k + 1) & 15, w2 = (k + 2) & 15, w3i = (k + 3) & 15;
            const int pB = gb + (((w1 & 3) << 2) | (w1 >> 2));
            const int pC = gb + (((w2 & 3) << 2) | (w2 >> 2));
            const int pD = gb + (((w3i & 3) << 2) | (w3i >> 2));
            s0 = fmaf(yr[pA], __ldg(w + k + 0), s0);
            s1 = fmaf(yr[pB], __ldg(w + k + 1), s1);
            s2 = fmaf(yr[pC], __ldg(w + k + 2), s2);
            s3 = fmaf(yr[pD], __ldg(w + k + 3), s3);
        }
        float acc = ((s0 + s1) + (s2 + s3)) + __ldg(b3 + s);
        g_partial[(size_t)a * 1024 + bbase + tid] = celu_f(acc);
    }
}

// ---------------- deterministic two-stage reduction ----------------
__global__ void reduce1() {
    int b = blockIdx.x * 256 + threadIdx.x;
    int ag = blockIdx.y;
    float acc = 0.f;
#pragma unroll
    for (int i = 0; i < 32; i++) acc += g_partial[(size_t)(ag * 32 + i) * 1024 + b];
    g_red[ag * 1024 + b] = acc;
}
__global__ void reduce2(float* __restrict__ out) {
    int b = blockIdx.x * 256 + threadIdx.x;
    float acc = 0.f;
#pragma unroll
    for (int g = 0; g < 8; g++) acc += g_red[g * 1024 + b];
    out[b] = acc;
}

extern "C" void kernel_launch(void* const* d_in, const int* in_sizes, int n_in,
                              void* d_out, int out_size) {
    const float* fullaev = (const float*)d_in[0];
    const int*   species = (const int*)d_in[1];
    const float* W0 = (const float*)d_in[2];
    const float* b0 = (const float*)d_in[3];
    const float* W1 = (const float*)d_in[4];
    const float* b1 = (const float*)d_in[5];
    const float* W2 = (const float*)d_in[6];
    const float* b2 = (const float*)d_in[7];
    const float* W3 = (const float*)d_in[8];
    const float* b3 = (const float*)d_in[9];

    prep_w<384, 256, 0><<<(4 * 384 * 256 + 255) / 256, 256>>>(W0);
    prep_w<256, 192, 1><<<(4 * 256 * 192 + 255) / 256, 256>>>(W1);
    prep_w<192, 160, 2><<<(4 * 192 * 160 + 255) / 256, 256>>>(W2);

    cudaFuncSetAttribute(aev_mlp_mma, cudaFuncAttributeMaxDynamicSharedMemorySize, SMEM_BYTES);
    dim3 grid(8, 256);   // (B-tiles of 128, atoms)
    aev_mlp_mma<<<grid, 512, SMEM_BYTES>>>(fullaev, species, b0, b1, b2, W3, b3);

    reduce1<<<dim3(4, 8), 256>>>();
    reduce2<<<4, 256>>>((float*)d_out);
}

// round 15
// speedup vs baseline: 1.4482x; 1.0261x over previous
#include <cuda_runtime.h>
#include <cstdint>
#include <math.h>

#define ALPHA_CELU 0.1f

// ---------------- device scratch ----------------
__device__ float g_Wp0[4 * 24 * 256 * 16];   // [s][chunk][n][16 perm k]  (tf32-rounded)
__device__ float g_Wp1[4 * 16 * 192 * 16];
__device__ float g_Wp2[4 * 12 * 160 * 16];
__device__ float g_partial[256 * 1024];      // [atom][b]
__device__ float g_red[8 * 1024];

// ---------------- helpers ----------------
// Branchless CELU: max(x,0) + min(0, alpha*(exp(x/alpha)-1)).
__device__ __forceinline__ float celu_f(float x) {
    float e = __expf(x * (1.f / ALPHA_CELU));
    return fmaxf(x, 0.f) + fminf(0.f, ALPHA_CELU * (e - 1.f));
}
__device__ __forceinline__ uint32_t tf32r(float x) {   // RNA round to tf32
    uint32_t u;
    asm("cvt.rna.tf32.f32 %0, %1;" : "=r"(u) : "f"(x));
    return u;
}
__device__ __forceinline__ float tf32rf(float x) { return __uint_as_float(tf32r(x)); }
__device__ __forceinline__ uint32_t smem_u32(const void* p) {
    uint32_t a;
    asm("{ .reg .u64 t; cvta.to.shared.u64 t, %1; cvt.u32.u64 %0, t; }" : "=r"(a) : "l"(p));
    return a;
}
__device__ __forceinline__ void mma_tf32(float c[4],
                                         uint32_t a0, uint32_t a1, uint32_t a2, uint32_t a3,
                                         uint32_t b0, uint32_t b1) {
    asm volatile("mma.sync.aligned.m16n8k8.row.col.f32.tf32.tf32.f32 "
                 "{%0,%1,%2,%3}, {%4,%5,%6,%7}, {%8,%9}, {%0,%1,%2,%3};"
                 : "+f"(c[0]), "+f"(c[1]), "+f"(c[2]), "+f"(c[3])
                 : "r"(a0), "r"(a1), "r"(a2), "r"(a3), "r"(b0), "r"(b1));
}
#define CP_ASYNC16(dst, src) \
    asm volatile("cp.async.ca.shared.global [%0], [%1], 16;" :: "r"(dst), "l"(src))
#define CP_COMMIT() asm volatile("cp.async.commit_group;" ::: "memory")
#define CP_WAIT1()  asm volatile("cp.async.wait_group 1;" ::: "memory")

// ---------------- smem layout (floats) ----------------
// Ys: 128 x 272 only (139264 B).  X ring (L0): 3 GROUPS x 4 chunks x 2560 floats
// = 30720 floats (122880 B), OVERLAYS Ys rows 0..112.  No W smem (B via __ldg).
#define LDY 272
#define SMEM_FLOATS (128 * LDY)           // 34816 floats
#define SMEM_BYTES (SMEM_FLOATS * 4)      // 139264 B

// ---------------- weight prep: [S,K,N] -> [s][k/16][n][perm(k&15)] tf32 ----------------
template<int K, int N, int WHICH>
__global__ void prep_w(const float* __restrict__ W) {
    int i = blockIdx.x * blockDim.x + threadIdx.x;
    if (i >= 4 * K * N) return;
    float* dst = (WHICH == 0) ? g_Wp0 : (WHICH == 1) ? g_Wp1 : g_Wp2;
    int n = i % N, k = (i / N) % K, s = i / (N * K);
    int chunk = k >> 4, w = k & 15;
    int p = ((w & 3) << 2) | (w >> 2);
    dst[((size_t)(s * (K / 16) + chunk) * N + n) * 16 + p] = __uint_as_float(tf32r(W[i]));
}

// ---------------- shared epilogue: +bias, celu, (round), permuted store to Ys ----------
template<int N, bool ROUND, int NT>
__device__ __forceinline__ void epilogue_store(
    float acc[2][NT][4], const float* __restrict__ bg, float* __restrict__ Ys,
    int m_idx, int n_idx, int q, int g4)
{
#pragma unroll
    for (int f = 0; f < 2; f++) {
#pragma unroll
        for (int t = 0; t < NT; t++) {
            const int r = m_idx * 32 + f * 16 + g4;
            const int cn = n_idx * (N / 4) + t * 8 + 2 * q;
            const float bv0 = __ldg(bg + cn), bv1 = __ldg(bg + cn + 1);
            float v0 = celu_f(acc[f][t][0] + bv0);
            float v1 = celu_f(acc[f][t][1] + bv1);
            float v2 = celu_f(acc[f][t][2] + bv0);
            float v3 = celu_f(acc[f][t][3] + bv1);
            if (ROUND) {
                v0 = tf32rf(v0); v1 = tf32rf(v1);
                v2 = tf32rf(v2); v3 = tf32rf(v3);
            }
            const int w0 = cn & 15, w1 = (cn + 1) & 15;
            const int p0 = (cn & ~15) + (((w0 & 3) << 2) | (w0 >> 2));
            const int p1 = (cn & ~15) + (((w1 & 3) << 2) | (w1 >> 2));
            Ys[r * LDY + p0] = v0;
            Ys[r * LDY + p1] = v1;
            Ys[(r + 8) * LDY + p0] = v2;
            Ys[(r + 8) * LDY + p1] = v3;
        }
    }
}

// ---------------- MMA for one chunk (plain; B direct from L2/L1) -------------------
template<int N, int NT>
__device__ __forceinline__ void mma_chunk(
    float acc[2][NT][4], const float* __restrict__ Wb,
    const float4 a0[2], const float4 a1[2], int n_idx, int q, int g4)
{
#pragma unroll
    for (int t = 0; t < NT; t++) {
        const int nb = n_idx * (N / 4) + t * 8 + g4;
        float4 bv = __ldg((const float4*)(Wb + nb * 16 + 4 * q));
#pragma unroll
        for (int f = 0; f < 2; f++) {
            mma_tf32(acc[f][t],
                     __float_as_uint(a0[f].x), __float_as_uint(a1[f].x),
                     __float_as_uint(a0[f].y), __float_as_uint(a1[f].y),
                     __float_as_uint(bv.x), __float_as_uint(bv.y));
            mma_tf32(acc[f][t],
                     __float_as_uint(a0[f].z), __float_as_uint(a1[f].z),
                     __float_as_uint(a0[f].w), __float_as_uint(a1[f].w),
                     __float_as_uint(bv.z), __float_as_uint(bv.w));
        }
    }
}

// ---------------- MMA for one chunk with explicit B-load batching (4 ahead) --------
template<int N, int NT>
__device__ __forceinline__ void mma_chunk_batched(
    float acc[2][NT][4], const float* __restrict__ Wb,
    const float4 a0[2], const float4 a1[2], int n_idx, int q, int g4)
{
    constexpr int NB = (NT + 3) / 4;
    float4 bva[4], bvb[4];
    const float* wbase = Wb + (size_t)(n_idx * (N / 4) + g4) * 16 + 4 * q;

#pragma unroll
    for (int t = 0; t < 4; t++)
        if (t < NT) bva[t] = __ldg((const float4*)(wbase + t * 128));

#pragma unroll
    for (int b = 0; b < NB; b++) {
        const int base = 4 * b;
#pragma unroll
        for (int t = 0; t < 4; t++)
            if (base + 4 + t < NT) bvb[t] = __ldg((const float4*)(wbase + (base + 4 + t) * 128));
#pragma unroll
        for (int t = 0; t < 4; t++) {
            if (base + t < NT) {
                const float4 bv = bva[t];
#pragma unroll
                for (int f = 0; f < 2; f++) {
                    mma_tf32(acc[f][base + t],
                             __float_as_uint(a0[f].x), __float_as_uint(a1[f].x),
                             __float_as_uint(a0[f].y), __float_as_uint(a1[f].y),
                             __float_as_uint(bv.x), __float_as_uint(bv.y));
                    mma_tf32(acc[f][base + t],
                             __float_as_uint(a0[f].z), __float_as_uint(a1[f].z),
                             __float_as_uint(a0[f].w), __float_as_uint(a1[f].w),
                             __float_as_uint(bv.z), __float_as_uint(bv.w));
                }
            }
        }
#pragma unroll
        for (int t = 0; t < 4; t++) bva[t] = bvb[t];
    }
}

// ---------------- layer 0: X streamed in GROUPS of 4 chunks, 3-group ring ----------
__device__ __forceinline__ void layer0_run(
    const float* __restrict__ Wp, const float* __restrict__ bg,
    const float* __restrict__ xg,
    float* __restrict__ Ys, const float* __restrict__ XcF, uint32_t xcU,
    int tid, int lane, int m_idx, int n_idx)
{
    constexpr int NT = 8, NG = 6;             // N=256, K=384: 24 chunks = 6 groups of 4

    float acc[2][NT][4];
#pragma unroll
    for (int f = 0; f < 2; f++)
#pragma unroll
        for (int t = 0; t < NT; t++)
#pragma unroll
            for (int j = 0; j < 4; j++) acc[f][t][j] = 0.f;

    const int xrow = tid >> 2, xblk = tid & 3;   // 512 thr = 128 rows x 4 k-quads
    const int q = lane & 3, g4 = lane >> 2;

    auto stageX = [&](int c) {   // chunk c -> group slot (c/4)%3, sub-slot c%4
        const uint32_t xdst = xcU + (uint32_t)((c >> 2) % 3) * 40960u
                                  + (uint32_t)(c & 3) * 10240u;
        const float* src = xg + (size_t)xrow * 98304 + c * 16 + xblk * 4;
        CP_ASYNC16(xdst + (uint32_t)(xrow * 80 + xblk * 16), src);
    };
    // Raw fp32 X fragments (no CVT): MMA truncates to tf32 internally.
    auto load_frags = [&](int c, float4 a0[2], float4 a1[2]) {
        const float* Xs = XcF + ((c >> 2) % 3) * 10240 + (c & 3) * 2560;
#pragma unroll
        for (int f = 0; f < 2; f++) {
            const float* p0 = Xs + (m_idx * 32 + f * 16 + g4) * 20 + q;
            const float* p1 = p0 + 8 * 20;
            a0[f].x = p0[0];  a0[f].y = p0[4];
            a0[f].z = p0[8];  a0[f].w = p0[12];
            a1[f].x = p1[0];  a1[f].y = p1[4];
            a1[f].z = p1[8];  a1[f].w = p1[12];
        }
    };

    // prologue: groups 0 and 1 in flight
#pragma unroll
    for (int j = 0; j < 4; j++) stageX(j);
    CP_COMMIT();
#pragma unroll
    for (int j = 4; j < 8; j++) stageX(j);
    CP_COMMIT();

#pragma unroll
    for (int g = 0; g < NG; g++) {
        CP_WAIT1();                 // group g landed (only group g+1 may be pending)
        __syncthreads();            // publish group g; all reads of group g-1 complete

        if (g + 2 < NG) {           // stage group g+2 into slot (g+2)%3 = (g-1)%3
#pragma unroll
            for (int j = 0; j < 4; j++) stageX(4 * (g + 2) + j);
        }
        CP_COMMIT();                // unconditional: keeps wait accounting exact

        // 4 chunks, barrier-free, with A-fragment register prefetch
        float4 a0[2], a1[2];
        load_frags(4 * g, a0, a1);
#pragma unroll
        for (int j = 0; j < 4; j++) {
            const int c = 4 * g + j;
            float4 na0[2], na1[2];
            if (j < 3) load_frags(c + 1, na0, na1);
            mma_chunk<256, NT>(acc, Wp + (size_t)c * 4096, a0, a1, n_idx, q, g4);
            if (j < 3) {
                a0[0] = na0[0]; a0[1] = na0[1];
                a1[0] = na1[0]; a1[1] = na1[1];
            }
        }
    }
    __syncthreads();   // all X reads done before epilogue overwrites Ys

    epilogue_store<256, true, NT>(acc, bg, Ys, m_idx, n_idx, q, g4);
    __syncthreads();
}

// ---------------- layers 1/2: A resident in Ys, barrier-free, batched B loads ------
template<int K, int N, bool ROUND>
__device__ __forceinline__ void layerR_run(
    const float* __restrict__ Wp, const float* __restrict__ bg,
    float* __restrict__ Ys,
    int lane, int m_idx, int n_idx)
{
    constexpr int NT = N / 32;
    constexpr int NC = K / 16;

    float acc[2][NT][4];
#pragma unroll
    for (int f = 0; f < 2; f++)
#pragma unroll
        for (int t = 0; t < NT; t++)
#pragma unroll
            for (int j = 0; j < 4; j++) acc[f][t][j] = 0.f;

    const int q = lane & 3, g4 = lane >> 2;

    auto load_frags = [&](int c, float4 a0[2], float4 a1[2]) {
        const int colb = c * 16 + 4 * q;
#pragma unroll
        for (int f = 0; f < 2; f++) {
            const float* p0 = Ys + (m_idx * 32 + f * 16 + g4) * LDY + colb;
            a0[f] = *(const float4*)p0;
            a1[f] = *(const float4*)(p0 + 8 * LDY);
        }
    };

    float4 a0[2], a1[2];
    load_frags(0, a0, a1);

#pragma unroll 4
    for (int c = 0; c < NC; c++) {
        float4 na0[2], na1[2];
        if (c + 1 < NC) load_frags(c + 1, na0, na1);
        mma_chunk_batched<N, NT>(acc, Wp + (size_t)c * (N * 16), a0, a1, n_idx, q, g4);
        if (c + 1 < NC) {
            a0[0] = na0[0]; a0[1] = na0[1];
            a1[0] = na1[0]; a1[1] = na1[1];
        }
    }
    __syncthreads();   // all Ys reads done before epilogue overwrites Ys

    epilogue_store<N, ROUND, NT>(acc, bg, Ys, m_idx, n_idx, q, g4);
    __syncthreads();
}

// ---------------- fused kernel ----------------
__global__ void __launch_bounds__(512, 1)
aev_mlp_mma(const float* __restrict__ fullaev, const int* __restrict__ species,
            const float* __restrict__ b0, const float* __restrict__ b1,
            const float* __restrict__ b2,
            const float* __restrict__ W3, const float* __restrict__ b3)
{
    extern __shared__ float sm[];
    float* Ys = sm;
    const float* XcF = sm;                  // X ring overlays Ys during L0
    const uint32_t xcU = smem_u32(sm);

    const int a = blockIdx.y;
    const int bbase = blockIdx.x * 128;
    const int tid = threadIdx.x;
    const int lane = tid & 31, wid = tid >> 5;
    const int m_idx = wid >> 2, n_idx = wid & 3;
    const int s = species[a];
    const float* xg = fullaev + (size_t)bbase * 98304 + (size_t)a * 384;

    layer0_run(g_Wp0 + (size_t)s * (24 * 256 * 16), b0 + s * 256, xg,
               Ys, XcF, xcU, tid, lane, m_idx, n_idx);
    layerR_run<256, 192, true >(g_Wp1 + (size_t)s * (16 * 192 * 16), b1 + s * 192,
                                Ys, lane, m_idx, n_idx);
    layerR_run<192, 160, false>(g_Wp2 + (size_t)s * (12 * 160 * 16), b2 + s * 160,
                                Ys, lane, m_idx, n_idx);

    // ---- layer 3: dot(Y2[r, 0:160], w3) + b3, celu ----
    if (tid < 128) {
        const float* w = W3 + s * 160;
        float s0 = 0.f, s1 = 0.f, s2 = 0.f, s3 = 0.f;
        const float* yr = Ys + tid * LDY;
#pragma unroll
        for (int k = 0; k < 160; k += 4) {
            const int gb = k & ~15;
            const int w0 = k & 15;
            const int pA = gb + (((w0 & 3) << 2) | (w0 >> 2));
            const int w1 = (k + 1) & 15, w2 = (k + 2) & 15, w3i = (k + 3) & 15;
            const int pB = gb + (((w1 & 3) << 2) | (w1 >> 2));
            const int pC = gb + (((w2 & 3) << 2) | (w2 >> 2));
            const int pD = gb + (((w3i & 3) << 2) | (w3i >> 2));
            s0 = fmaf(yr[pA], __ldg(w + k + 0), s0);
            s1 = fmaf(yr[pB], __ldg(w + k + 1), s1);
            s2 = fmaf(yr[pC], __ldg(w + k + 2), s2);
            s3 = fmaf(yr[pD], __ldg(w + k + 3), s3);
        }
        float acc = ((s0 + s1) + (s2 + s3)) + __ldg(b3 + s);
        g_partial[(size_t)a * 1024 + bbase + tid] = celu_f(acc);
    }
}

// ---------------- deterministic two-stage reduction ----------------
__global__ void reduce1() {
    int b = blockIdx.x * 256 + threadIdx.x;
    int ag = blockIdx.y;
    float acc = 0.f;
#pragma unroll
    for (int i = 0; i < 32; i++) acc += g_partial[(size_t)(ag * 32 + i) * 1024 + b];
    g_red[ag * 1024 + b] = acc;
}
__global__ void reduce2(float* __restrict__ out) {
    int b = blockIdx.x * 256 + threadIdx.x;
    float acc = 0.f;
#pragma unroll
    for (int g = 0; g < 8; g++) acc += g_red[g * 1024 + b];
    out[b] = acc;
}

extern "C" void kernel_launch(void* const* d_in, const int* in_sizes, int n_in,
                              void* d_out, int out_size) {
    const float* fullaev = (const float*)d_in[0];
    const int*   species = (const int*)d_in[1];
    const float* W0 = (const float*)d_in[2];
    const float* b0 = (const float*)d_in[3];
    const float* W1 = (const float*)d_in[4];
    const float* b1 = (const float*)d_in[5];
    const float* W2 = (const float*)d_in[6];
    const float* b2 = (const float*)d_in[7];
    const float* W3 = (const float*)d_in[8];
    const float* b3 = (const float*)d_in[9];

    prep_w<384, 256, 0><<<(4 * 384 * 256 + 255) / 256, 256>>>(W0);
    prep_w<256, 192, 1><<<(4 * 256 * 192 + 255) / 256, 256>>>(W1);
    prep_w<192, 160, 2><<<(4 * 192 * 160 + 255) / 256, 256>>>(W2);

    cudaFuncSetAttribute(aev_mlp_mma, cudaFuncAttributeMaxDynamicSharedMemorySize, SMEM_BYTES);
    dim3 grid(8, 256);   // (B-tiles of 128, atoms)
    aev_mlp_mma<<<grid, 512, SMEM_BYTES>>>(fullaev, species, b0, b1, b2, W3, b3);

    reduce1<<<dim3(4, 8), 256>>>();
    reduce2<<<4, 256>>>((float*)d_out);
}

// round 16
// speedup vs baseline: 1.4509x; 1.0018x over previous
#include <cuda_runtime.h>
#include <cstdint>
#include <math.h>

#define ALPHA_CELU 0.1f

// ---------------- device scratch ----------------
__device__ float g_Wp0[4 * 24 * 256 * 16];   // [s][chunk][n][16 perm k]  (tf32-rounded)
__device__ float g_Wp1[4 * 16 * 192 * 16];
__device__ float g_Wp2[4 * 12 * 160 * 16];
__device__ float g_partial[256 * 1024];      // [atom][b]
__device__ float g_red[8 * 1024];

// ---------------- helpers ----------------
// Branchless CELU: max(x,0) + min(0, alpha*(exp(x/alpha)-1)).
__device__ __forceinline__ float celu_f(float x) {
    float e = __expf(x * (1.f / ALPHA_CELU));
    return fmaxf(x, 0.f) + fminf(0.f, ALPHA_CELU * (e - 1.f));
}
__device__ __forceinline__ uint32_t tf32r(float x) {   // RNA round to tf32
    uint32_t u;
    asm("cvt.rna.tf32.f32 %0, %1;" : "=r"(u) : "f"(x));
    return u;
}
__device__ __forceinline__ float tf32rf(float x) { return __uint_as_float(tf32r(x)); }
__device__ __forceinline__ uint32_t smem_u32(const void* p) {
    uint32_t a;
    asm("{ .reg .u64 t; cvta.to.shared.u64 t, %1; cvt.u32.u64 %0, t; }" : "=r"(a) : "l"(p));
    return a;
}
__device__ __forceinline__ void mma_tf32(float c[4],
                                         uint32_t a0, uint32_t a1, uint32_t a2, uint32_t a3,
                                         uint32_t b0, uint32_t b1) {
    asm volatile("mma.sync.aligned.m16n8k8.row.col.f32.tf32.tf32.f32 "
                 "{%0,%1,%2,%3}, {%4,%5,%6,%7}, {%8,%9}, {%0,%1,%2,%3};"
                 : "+f"(c[0]), "+f"(c[1]), "+f"(c[2]), "+f"(c[3])
                 : "r"(a0), "r"(a1), "r"(a2), "r"(a3), "r"(b0), "r"(b1));
}
#define CP_ASYNC16(dst, src) \
    asm volatile("cp.async.ca.shared.global [%0], [%1], 16;" :: "r"(dst), "l"(src))
#define CP_COMMIT() asm volatile("cp.async.commit_group;" ::: "memory")
#define CP_WAIT1()  asm volatile("cp.async.wait_group 1;" ::: "memory")

// ---------------- smem layout (floats) ----------------
// Ys: 128 x 272 only (139264 B).  X ring (L0): 3 GROUPS x 4 chunks x 2560 floats
// = 30720 floats (122880 B), OVERLAYS Ys rows 0..112.  No W smem (B via __ldg).
#define LDY 272
#define SMEM_FLOATS (128 * LDY)           // 34816 floats
#define SMEM_BYTES (SMEM_FLOATS * 4)      // 139264 B

// ---------------- weight prep: [S,K,N] -> [s][k/16][n][perm(k&15)] tf32 ----------------
template<int K, int N, int WHICH>
__global__ void prep_w(const float* __restrict__ W) {
    int i = blockIdx.x * blockDim.x + threadIdx.x;
    if (i >= 4 * K * N) return;
    float* dst = (WHICH == 0) ? g_Wp0 : (WHICH == 1) ? g_Wp1 : g_Wp2;
    int n = i % N, k = (i / N) % K, s = i / (N * K);
    int chunk = k >> 4, w = k & 15;
    int p = ((w & 3) << 2) | (w >> 2);
    dst[((size_t)(s * (K / 16) + chunk) * N + n) * 16 + p] = __uint_as_float(tf32r(W[i]));
}

// ---------------- shared epilogue: +bias, celu, (round), permuted store to Ys ----------
template<int N, bool ROUND, int NT>
__device__ __forceinline__ void epilogue_store(
    float acc[2][NT][4], const float* __restrict__ bg, float* __restrict__ Ys,
    int m_idx, int n_idx, int q, int g4)
{
#pragma unroll
    for (int f = 0; f < 2; f++) {
#pragma unroll
        for (int t = 0; t < NT; t++) {
            const int r = m_idx * 32 + f * 16 + g4;
            const int cn = n_idx * (N / 4) + t * 8 + 2 * q;
            const float bv0 = __ldg(bg + cn), bv1 = __ldg(bg + cn + 1);
            float v0 = celu_f(acc[f][t][0] + bv0);
            float v1 = celu_f(acc[f][t][1] + bv1);
            float v2 = celu_f(acc[f][t][2] + bv0);
            float v3 = celu_f(acc[f][t][3] + bv1);
            if (ROUND) {
                v0 = tf32rf(v0); v1 = tf32rf(v1);
                v2 = tf32rf(v2); v3 = tf32rf(v3);
            }
            const int w0 = cn & 15, w1 = (cn + 1) & 15;
            const int p0 = (cn & ~15) + (((w0 & 3) << 2) | (w0 >> 2));
            const int p1 = (cn & ~15) + (((w1 & 3) << 2) | (w1 >> 2));
            Ys[r * LDY + p0] = v0;
            Ys[r * LDY + p1] = v1;
            Ys[(r + 8) * LDY + p0] = v2;
            Ys[(r + 8) * LDY + p1] = v3;
        }
    }
}

// ---------------- MMA helper: one n8-tile pair of k8 steps -------------------------
template<int NT>
__device__ __forceinline__ void mma_tile(
    float acc[2][NT][4], int t, const float4& bv,
    const float4 a0[2], const float4 a1[2])
{
#pragma unroll
    for (int f = 0; f < 2; f++) {
        mma_tf32(acc[f][t],
                 __float_as_uint(a0[f].x), __float_as_uint(a1[f].x),
                 __float_as_uint(a0[f].y), __float_as_uint(a1[f].y),
                 __float_as_uint(bv.x), __float_as_uint(bv.y));
        mma_tf32(acc[f][t],
                 __float_as_uint(a0[f].z), __float_as_uint(a1[f].z),
                 __float_as_uint(a0[f].w), __float_as_uint(a1[f].w),
                 __float_as_uint(bv.z), __float_as_uint(bv.w));
    }
}

// ---------------- MMA chunk with 2-ahead (pair) B batching — low reg cost ----------
template<int N, int NT>
__device__ __forceinline__ void mma_chunk_b2(
    float acc[2][NT][4], const float* __restrict__ Wb,
    const float4 a0[2], const float4 a1[2], int n_idx, int q, int g4)
{
    static_assert(NT % 2 == 0, "NT even");
    const float* wbase = Wb + (size_t)(n_idx * (N / 4) + g4) * 16 + 4 * q;
    float4 bva[2], bvb[2];
    bva[0] = __ldg((const float4*)(wbase));
    bva[1] = __ldg((const float4*)(wbase + 128));
#pragma unroll
    for (int p = 0; p < NT / 2; p++) {
        if (p + 1 < NT / 2) {
            bvb[0] = __ldg((const float4*)(wbase + (2 * p + 2) * 128));
            bvb[1] = __ldg((const float4*)(wbase + (2 * p + 3) * 128));
        }
        mma_tile<NT>(acc, 2 * p, bva[0], a0, a1);
        mma_tile<NT>(acc, 2 * p + 1, bva[1], a0, a1);
        bva[0] = bvb[0]; bva[1] = bvb[1];
    }
}

// ---------------- MMA chunk with 4-ahead B batching (layers 1/2) -------------------
template<int N, int NT>
__device__ __forceinline__ void mma_chunk_batched(
    float acc[2][NT][4], const float* __restrict__ Wb,
    const float4 a0[2], const float4 a1[2], int n_idx, int q, int g4)
{
    constexpr int NB = (NT + 3) / 4;
    float4 bva[4], bvb[4];
    const float* wbase = Wb + (size_t)(n_idx * (N / 4) + g4) * 16 + 4 * q;

#pragma unroll
    for (int t = 0; t < 4; t++)
        if (t < NT) bva[t] = __ldg((const float4*)(wbase + t * 128));

#pragma unroll
    for (int b = 0; b < NB; b++) {
        const int base = 4 * b;
#pragma unroll
        for (int t = 0; t < 4; t++)
            if (base + 4 + t < NT) bvb[t] = __ldg((const float4*)(wbase + (base + 4 + t) * 128));
#pragma unroll
        for (int t = 0; t < 4; t++)
            if (base + t < NT) mma_tile<NT>(acc, base + t, bva[t], a0, a1);
#pragma unroll
        for (int t = 0; t < 4; t++) bva[t] = bvb[t];
    }
}

// ---------------- layer 0: X streamed in GROUPS of 4 chunks, 3-group ring ----------
__device__ __forceinline__ void layer0_run(
    const float* __restrict__ Wp, const float* __restrict__ bg,
    const float* __restrict__ xg,
    float* __restrict__ Ys, const float* __restrict__ XcF, uint32_t xcU,
    int tid, int lane, int m_idx, int n_idx)
{
    constexpr int NT = 8, NG = 6;             // N=256, K=384: 24 chunks = 6 groups of 4

    float acc[2][NT][4];
#pragma unroll
    for (int f = 0; f < 2; f++)
#pragma unroll
        for (int t = 0; t < NT; t++)
#pragma unroll
            for (int j = 0; j < 4; j++) acc[f][t][j] = 0.f;

    const int xrow = tid >> 2, xblk = tid & 3;   // 512 thr = 128 rows x 4 k-quads
    const int q = lane & 3, g4 = lane >> 2;

    auto stageX = [&](int c) {   // chunk c -> group slot (c/4)%3, sub-slot c%4
        const uint32_t xdst = xcU + (uint32_t)((c >> 2) % 3) * 40960u
                                  + (uint32_t)(c & 3) * 10240u;
        const float* src = xg + (size_t)xrow * 98304 + c * 16 + xblk * 4;
        CP_ASYNC16(xdst + (uint32_t)(xrow * 80 + xblk * 16), src);
    };
    // Raw fp32 X fragments (no CVT): MMA truncates to tf32 internally.
    auto load_frags = [&](int c, float4 a0[2], float4 a1[2]) {
        const float* Xs = XcF + ((c >> 2) % 3) * 10240 + (c & 3) * 2560;
#pragma unroll
        for (int f = 0; f < 2; f++) {
            const float* p0 = Xs + (m_idx * 32 + f * 16 + g4) * 20 + q;
            const float* p1 = p0 + 8 * 20;
            a0[f].x = p0[0];  a0[f].y = p0[4];
            a0[f].z = p0[8];  a0[f].w = p0[12];
            a1[f].x = p1[0];  a1[f].y = p1[4];
            a1[f].z = p1[8];  a1[f].w = p1[12];
        }
    };

    // prologue: groups 0 and 1 in flight
#pragma unroll
    for (int j = 0; j < 4; j++) stageX(j);
    CP_COMMIT();
#pragma unroll
    for (int j = 4; j < 8; j++) stageX(j);
    CP_COMMIT();

#pragma unroll
    for (int g = 0; g < NG; g++) {
        CP_WAIT1();                 // group g landed (only group g+1 may be pending)
        __syncthreads();            // publish group g; all reads of group g-1 complete

        if (g + 2 < NG) {           // stage group g+2 into slot (g+2)%3 = (g-1)%3
#pragma unroll
            for (int j = 0; j < 4; j++) stageX(4 * (g + 2) + j);
        }
        CP_COMMIT();                // unconditional: keeps wait accounting exact

        // 4 chunks, barrier-free, with A-fragment register prefetch + paired B batch
        float4 a0[2], a1[2];
        load_frags(4 * g, a0, a1);
#pragma unroll
        for (int j = 0; j < 4; j++) {
            const int c = 4 * g + j;
            float4 na0[2], na1[2];
            if (j < 3) load_frags(c + 1, na0, na1);
            mma_chunk_b2<256, NT>(acc, Wp + (size_t)c * 4096, a0, a1, n_idx, q, g4);
            if (j < 3) {
                a0[0] = na0[0]; a0[1] = na0[1];
                a1[0] = na1[0]; a1[1] = na1[1];
            }
        }
    }
    __syncthreads();   // all X reads done before epilogue overwrites Ys

    epilogue_store<256, true, NT>(acc, bg, Ys, m_idx, n_idx, q, g4);
    __syncthreads();
}

// ---------------- layers 1/2: A resident in Ys, barrier-free, batched B loads ------
template<int K, int N, bool ROUND>
__device__ __forceinline__ void layerR_run(
    const float* __restrict__ Wp, const float* __restrict__ bg,
    float* __restrict__ Ys,
    int lane, int m_idx, int n_idx)
{
    constexpr int NT = N / 32;
    constexpr int NC = K / 16;

    float acc[2][NT][4];
#pragma unroll
    for (int f = 0; f < 2; f++)
#pragma unroll
        for (int t = 0; t < NT; t++)
#pragma unroll
            for (int j = 0; j < 4; j++) acc[f][t][j] = 0.f;

    const int q = lane & 3, g4 = lane >> 2;

    auto load_frags = [&](int c, float4 a0[2], float4 a1[2]) {
        const int colb = c * 16 + 4 * q;
#pragma unroll
        for (int f = 0; f < 2; f++) {
            const float* p0 = Ys + (m_idx * 32 + f * 16 + g4) * LDY + colb;
            a0[f] = *(const float4*)p0;
            a1[f] = *(const float4*)(p0 + 8 * LDY);
        }
    };

    float4 a0[2], a1[2];
    load_frags(0, a0, a1);

#pragma unroll 4
    for (int c = 0; c < NC; c++) {
        float4 na0[2], na1[2];
        if (c + 1 < NC) load_frags(c + 1, na0, na1);
        mma_chunk_batched<N, NT>(acc, Wp + (size_t)c * (N * 16), a0, a1, n_idx, q, g4);
        if (c + 1 < NC) {
            a0[0] = na0[0]; a0[1] = na0[1];
            a1[0] = na1[0]; a1[1] = na1[1];
        }
    }
    __syncthreads();   // all Ys reads done before epilogue overwrites Ys

    epilogue_store<N, ROUND, NT>(acc, bg, Ys, m_idx, n_idx, q, g4);
    __syncthreads();
}

// ---------------- fused kernel ----------------
__global__ void __launch_bounds__(512, 1)
aev_mlp_mma(const float* __restrict__ fullaev, const int* __restrict__ species,
            const float* __restrict__ b0, const float* __restrict__ b1,
            const float* __restrict__ b2,
            const float* __restrict__ W3, const float* __restrict__ b3)
{
    extern __shared__ float sm[];
    float* Ys = sm;
    const float* XcF = sm;                  // X ring overlays Ys during L0
    const uint32_t xcU = smem_u32(sm);

    const int a = blockIdx.y;
    const int bbase = blockIdx.x * 128;
    const int tid = threadIdx.x;
    const int lane = tid & 31, wid = tid >> 5;
    const int m_idx = wid >> 2, n_idx = wid & 3;
    const int s = species[a];
    const float* xg = fullaev + (size_t)bbase * 98304 + (size_t)a * 384;

    layer0_run(g_Wp0 + (size_t)s * (24 * 256 * 16), b0 + s * 256, xg,
               Ys, XcF, xcU, tid, lane, m_idx, n_idx);
    layerR_run<256, 192, true >(g_Wp1 + (size_t)s * (16 * 192 * 16), b1 + s * 192,
                                Ys, lane, m_idx, n_idx);
    layerR_run<192, 160, false>(g_Wp2 + (size_t)s * (12 * 160 * 16), b2 + s * 160,
                                Ys, lane, m_idx, n_idx);

    // ---- layer 3: dot(Y2[r, 0:160], w3) + b3, celu ----
    if (tid < 128) {
        const float* w = W3 + s * 160;
        float s0 = 0.f, s1 = 0.f, s2 = 0.f, s3 = 0.f;
        const float* yr = Ys + tid * LDY;
#pragma unroll
        for (int k = 0; k < 160; k += 4) {
            const int gb = k & ~15;
            const int w0 = k & 15;
            const int pA = gb + (((w0 & 3) << 2) | (w0 >> 2));
            const int w1 = (k + 1) & 15, w2 = (k + 2) & 15, w3i = (k + 3) & 15;
            const int pB = gb + (((w1 & 3) << 2) | (w1 >> 2));
            const int pC = gb + (((w2 & 3) << 2) | (w2 >> 2));
            const int pD = gb + (((w3i & 3) << 2) | (w3i >> 2));
            s0 = fmaf(yr[pA], __ldg(w + k + 0), s0);
            s1 = fmaf(yr[pB], __ldg(w + k + 1), s1);
            s2 = fmaf(yr[pC], __ldg(w + k + 2), s2);
            s3 = fmaf(yr[pD], __ldg(w + k + 3), s3);
        }
        float acc = ((s0 + s1) + (s2 + s3)) + __ldg(b3 + s);
        g_partial[(size_t)a * 1024 + bbase + tid] = celu_f(acc);
    }
}

// ---------------- deterministic two-stage reduction ----------------
__global__ void reduce1() {
    int b = blockIdx.x * 256 + threadIdx.x;
    int ag = blockIdx.y;
    float acc = 0.f;
#pragma unroll
    for (int i = 0; i < 32; i++) acc += g_partial[(size_t)(ag * 32 + i) * 1024 + b];
    g_red[ag * 1024 + b] = acc;
}
__global__ void reduce2(float* __restrict__ out) {
    int b = blockIdx.x * 256 + threadIdx.x;
    float acc = 0.f;
#pragma unroll
    for (int g = 0; g < 8; g++) acc += g_red[g * 1024 + b];
    out[b] = acc;
}

extern "C" void kernel_launch(void* const* d_in, const int* in_sizes, int n_in,
                              void* d_out, int out_size) {
    const float* fullaev = (const float*)d_in[0];
    const int*   species = (const int*)d_in[1];
    const float* W0 = (const float*)d_in[2];
    const float* b0 = (const float*)d_in[3];
    const float* W1 = (const float*)d_in[4];
    const float* b1 = (const float*)d_in[5];
    const float* W2 = (const float*)d_in[6];
    const float* b2 = (const float*)d_in[7];
    const float* W3 = (const float*)d_in[8];
    const float* b3 = (const float*)d_in[9];

    prep_w<384, 256, 0><<<(4 * 384 * 256 + 255) / 256, 256>>>(W0);
    prep_w<256, 192, 1><<<(4 * 256 * 192 + 255) / 256, 256>>>(W1);
    prep_w<192, 160, 2><<<(4 * 192 * 160 + 255) / 256, 256>>>(W2);

    cudaFuncSetAttribute(aev_mlp_mma, cudaFuncAttributeMaxDynamicSharedMemorySize, SMEM_BYTES);
    dim3 grid(8, 256);   // (B-tiles of 128, atoms)
    aev_mlp_mma<<<grid, 512, SMEM_BYTES>>>(fullaev, species, b0, b1, b2, W3, b3);

    reduce1<<<dim3(4, 8), 256>>>();
    reduce2<<<4, 256>>>((float*)d_out);
}

// round 17
// speedup vs baseline: 1.4617x; 1.0075x over previous
#include <cuda_runtime.h>
#include <cstdint>
#include <math.h>

#define ALPHA_CELU 0.1f

// ---------------- device scratch ----------------
__device__ float g_Wp0[4 * 24 * 256 * 16];   // [s][chunk][n][16 perm k]  (tf32-rounded)
__device__ float g_Wp1[4 * 16 * 192 * 16];
__device__ float g_Wp2[4 * 12 * 160 * 16];
__device__ float g_partial[256 * 1024];      // [atom][b]
__device__ float g_red[8 * 1024];

// ---------------- helpers ----------------
// Branchless CELU: max(x,0) + min(0, alpha*(exp(x/alpha)-1)).
__device__ __forceinline__ float celu_f(float x) {
    float e = __expf(x * (1.f / ALPHA_CELU));
    return fmaxf(x, 0.f) + fminf(0.f, ALPHA_CELU * (e - 1.f));
}
__device__ __forceinline__ uint32_t tf32r(float x) {   // RNA round to tf32
    uint32_t u;
    asm("cvt.rna.tf32.f32 %0, %1;" : "=r"(u) : "f"(x));
    return u;
}
__device__ __forceinline__ float tf32rf(float x) { return __uint_as_float(tf32r(x)); }
__device__ __forceinline__ uint32_t smem_u32(const void* p) {
    uint32_t a;
    asm("{ .reg .u64 t; cvta.to.shared.u64 t, %1; cvt.u32.u64 %0, t; }" : "=r"(a) : "l"(p));
    return a;
}
__device__ __forceinline__ void mma_tf32(float c[4],
                                         uint32_t a0, uint32_t a1, uint32_t a2, uint32_t a3,
                                         uint32_t b0, uint32_t b1) {
    asm volatile("mma.sync.aligned.m16n8k8.row.col.f32.tf32.tf32.f32 "
                 "{%0,%1,%2,%3}, {%4,%5,%6,%7}, {%8,%9}, {%0,%1,%2,%3};"
                 : "+f"(c[0]), "+f"(c[1]), "+f"(c[2]), "+f"(c[3])
                 : "r"(a0), "r"(a1), "r"(a2), "r"(a3), "r"(b0), "r"(b1));
}
#define CP_ASYNC16(dst, src) \
    asm volatile("cp.async.ca.shared.global [%0], [%1], 16;" :: "r"(dst), "l"(src))
#define CP_COMMIT() asm volatile("cp.async.commit_group;" ::: "memory")
#define CP_WAIT1()  asm volatile("cp.async.wait_group 1;" ::: "memory")

// ---------------- smem layout (floats) ----------------
// Ys: 128 x 272 only (139264 B).  X ring (L0): 3 GROUPS x 4 chunks x 2560 floats
// = 30720 floats (122880 B), OVERLAYS Ys rows 0..112.  No W smem (B via __ldg).
#define LDY 272
#define SMEM_FLOATS (128 * LDY)           // 34816 floats
#define SMEM_BYTES (SMEM_FLOATS * 4)      // 139264 B

// ---------------- weight prep: [S,K,N] -> [s][k/16][n][perm(k&15)] tf32 ----------------
template<int K, int N, int WHICH>
__global__ void prep_w(const float* __restrict__ W) {
    int i = blockIdx.x * blockDim.x + threadIdx.x;
    if (i >= 4 * K * N) return;
    float* dst = (WHICH == 0) ? g_Wp0 : (WHICH == 1) ? g_Wp1 : g_Wp2;
    int n = i % N, k = (i / N) % K, s = i / (N * K);
    int chunk = k >> 4, w = k & 15;
    int p = ((w & 3) << 2) | (w >> 2);
    dst[((size_t)(s * (K / 16) + chunk) * N + n) * 16 + p] = __uint_as_float(tf32r(W[i]));
}

// ---------------- shared epilogue: +bias, celu, (round), permuted store to Ys ----------
template<int N, bool ROUND, int NT>
__device__ __forceinline__ void epilogue_store(
    float acc[2][NT][4], const float* __restrict__ bg, float* __restrict__ Ys,
    int m_idx, int n_idx, int q, int g4)
{
#pragma unroll
    for (int f = 0; f < 2; f++) {
#pragma unroll
        for (int t = 0; t < NT; t++) {
            const int r = m_idx * 32 + f * 16 + g4;
            const int cn = n_idx * (N / 4) + t * 8 + 2 * q;
            const float bv0 = __ldg(bg + cn), bv1 = __ldg(bg + cn + 1);
            float v0 = celu_f(acc[f][t][0] + bv0);
            float v1 = celu_f(acc[f][t][1] + bv1);
            float v2 = celu_f(acc[f][t][2] + bv0);
            float v3 = celu_f(acc[f][t][3] + bv1);
            if (ROUND) {
                v0 = tf32rf(v0); v1 = tf32rf(v1);
                v2 = tf32rf(v2); v3 = tf32rf(v3);
            }
            const int w0 = cn & 15, w1 = (cn + 1) & 15;
            const int p0 = (cn & ~15) + (((w0 & 3) << 2) | (w0 >> 2));
            const int p1 = (cn & ~15) + (((w1 & 3) << 2) | (w1 >> 2));
            Ys[r * LDY + p0] = v0;
            Ys[r * LDY + p1] = v1;
            Ys[(r + 8) * LDY + p0] = v2;
            Ys[(r + 8) * LDY + p1] = v3;
        }
    }
}

// ---------------- MMA helper: one n8-tile pair of k8 steps -------------------------
template<int NT>
__device__ __forceinline__ void mma_tile(
    float acc[2][NT][4], int t, const float4& bv,
    const float4 a0[2], const float4 a1[2])
{
#pragma unroll
    for (int f = 0; f < 2; f++) {
        mma_tf32(acc[f][t],
                 __float_as_uint(a0[f].x), __float_as_uint(a1[f].x),
                 __float_as_uint(a0[f].y), __float_as_uint(a1[f].y),
                 __float_as_uint(bv.x), __float_as_uint(bv.y));
        mma_tf32(acc[f][t],
                 __float_as_uint(a0[f].z), __float_as_uint(a1[f].z),
                 __float_as_uint(a0[f].w), __float_as_uint(a1[f].w),
                 __float_as_uint(bv.z), __float_as_uint(bv.w));
    }
}

// ---------------- MMA chunk with 2-ahead (pair) B batching — low reg cost ----------
template<int N, int NT>
__device__ __forceinline__ void mma_chunk_b2(
    float acc[2][NT][4], const float* __restrict__ Wb,
    const float4 a0[2], const float4 a1[2], int n_idx, int q, int g4)
{
    static_assert(NT % 2 == 0, "NT even");
    const float* wbase = Wb + (size_t)(n_idx * (N / 4) + g4) * 16 + 4 * q;
    float4 bva[2], bvb[2];
    bva[0] = __ldg((const float4*)(wbase));
    bva[1] = __ldg((const float4*)(wbase + 128));
#pragma unroll
    for (int p = 0; p < NT / 2; p++) {
        if (p + 1 < NT / 2) {
            bvb[0] = __ldg((const float4*)(wbase + (2 * p + 2) * 128));
            bvb[1] = __ldg((const float4*)(wbase + (2 * p + 3) * 128));
        }
        mma_tile<NT>(acc, 2 * p, bva[0], a0, a1);
        mma_tile<NT>(acc, 2 * p + 1, bva[1], a0, a1);
        bva[0] = bvb[0]; bva[1] = bvb[1];
    }
}

// ---------------- MMA chunk with 4-ahead B batching (layers 1/2) -------------------
template<int N, int NT>
__device__ __forceinline__ void mma_chunk_batched(
    float acc[2][NT][4], const float* __restrict__ Wb,
    const float4 a0[2], const float4 a1[2], int n_idx, int q, int g4)
{
    constexpr int NB = (NT + 3) / 4;
    float4 bva[4], bvb[4];
    const float* wbase = Wb + (size_t)(n_idx * (N / 4) + g4) * 16 + 4 * q;

#pragma unroll
    for (int t = 0; t < 4; t++)
        if (t < NT) bva[t] = __ldg((const float4*)(wbase + t * 128));

#pragma unroll
    for (int b = 0; b < NB; b++) {
        const int base = 4 * b;
#pragma unroll
        for (int t = 0; t < 4; t++)
            if (base + 4 + t < NT) bvb[t] = __ldg((const float4*)(wbase + (base + 4 + t) * 128));
#pragma unroll
        for (int t = 0; t < 4; t++)
            if (base + t < NT) mma_tile<NT>(acc, base + t, bva[t], a0, a1);
#pragma unroll
        for (int t = 0; t < 4; t++) bva[t] = bvb[t];
    }
}

// ---------------- layer 0: X streamed in GROUPS of 4 chunks, 3-group ring ----------
__device__ __forceinline__ void layer0_run(
    const float* __restrict__ Wp, const float* __restrict__ bg,
    const float* __restrict__ xg,
    float* __restrict__ Ys, const float* __restrict__ XcF, uint32_t xcU,
    int tid, int lane, int m_idx, int n_idx)
{
    constexpr int NT = 8, NG = 6;             // N=256, K=384: 24 chunks = 6 groups of 4

    float acc[2][NT][4];
#pragma unroll
    for (int f = 0; f < 2; f++)
#pragma unroll
        for (int t = 0; t < NT; t++)
#pragma unroll
            for (int j = 0; j < 4; j++) acc[f][t][j] = 0.f;

    const int xrow = tid >> 2, xblk = tid & 3;   // 512 thr = 128 rows x 4 k-quads
    const int q = lane & 3, g4 = lane >> 2;

    auto stageX = [&](int c) {   // chunk c -> group slot (c/4)%3, sub-slot c%4
        const uint32_t xdst = xcU + (uint32_t)((c >> 2) % 3) * 40960u
                                  + (uint32_t)(c & 3) * 10240u;
        const float* src = xg + (size_t)xrow * 98304 + c * 16 + xblk * 4;
        CP_ASYNC16(xdst + (uint32_t)(xrow * 80 + xblk * 16), src);
    };
    // Raw fp32 X fragments (no CVT): MMA truncates to tf32 internally.
    auto load_frags = [&](int c, float4 a0[2], float4 a1[2]) {
        const float* Xs = XcF + ((c >> 2) % 3) * 10240 + (c & 3) * 2560;
#pragma unroll
        for (int f = 0; f < 2; f++) {
            const float* p0 = Xs + (m_idx * 32 + f * 16 + g4) * 20 + q;
            const float* p1 = p0 + 8 * 20;
            a0[f].x = p0[0];  a0[f].y = p0[4];
            a0[f].z = p0[8];  a0[f].w = p0[12];
            a1[f].x = p1[0];  a1[f].y = p1[4];
            a1[f].z = p1[8];  a1[f].w = p1[12];
        }
    };

    // prologue: groups 0 and 1 in flight
#pragma unroll
    for (int j = 0; j < 4; j++) stageX(j);
    CP_COMMIT();
#pragma unroll
    for (int j = 4; j < 8; j++) stageX(j);
    CP_COMMIT();

#pragma unroll
    for (int g = 0; g < NG; g++) {
        CP_WAIT1();                 // group g landed (only group g+1 may be pending)
        __syncthreads();            // publish group g; all reads of group g-1 complete

        if (g + 2 < NG) {           // stage group g+2 into slot (g+2)%3 = (g-1)%3
#pragma unroll
            for (int j = 0; j < 4; j++) stageX(4 * (g + 2) + j);
        }
        CP_COMMIT();                // unconditional: keeps wait accounting exact

        // 4 chunks, barrier-free, with A-fragment register prefetch + paired B batch
        float4 a0[2], a1[2];
        load_frags(4 * g, a0, a1);
#pragma unroll
        for (int j = 0; j < 4; j++) {
            const int c = 4 * g + j;
            float4 na0[2], na1[2];
            if (j < 3) load_frags(c + 1, na0, na1);
            mma_chunk_b2<256, NT>(acc, Wp + (size_t)c * 4096, a0, a1, n_idx, q, g4);
            if (j < 3) {
                a0[0] = na0[0]; a0[1] = na0[1];
                a1[0] = na1[0]; a1[1] = na1[1];
            }
        }
    }
    __syncthreads();   // all X reads done before epilogue overwrites Ys

    epilogue_store<256, true, NT>(acc, bg, Ys, m_idx, n_idx, q, g4);
    __syncthreads();
}

// ---------------- layers 1/2: A resident in Ys, barrier-free, batched B loads ------
// Chunk loop FULLY unrolled: ptxas schedules B LDG / A LDS across chunk boundaries.
template<int K, int N, bool ROUND>
__device__ __forceinline__ void layerR_run(
    const float* __restrict__ Wp, const float* __restrict__ bg,
    float* __restrict__ Ys,
    int lane, int m_idx, int n_idx)
{
    constexpr int NT = N / 32;
    constexpr int NC = K / 16;

    float acc[2][NT][4];
#pragma unroll
    for (int f = 0; f < 2; f++)
#pragma unroll
        for (int t = 0; t < NT; t++)
#pragma unroll
            for (int j = 0; j < 4; j++) acc[f][t][j] = 0.f;

    const int q = lane & 3, g4 = lane >> 2;

    auto load_frags = [&](int c, float4 a0[2], float4 a1[2]) {
        const int colb = c * 16 + 4 * q;
#pragma unroll
        for (int f = 0; f < 2; f++) {
            const float* p0 = Ys + (m_idx * 32 + f * 16 + g4) * LDY + colb;
            a0[f] = *(const float4*)p0;
            a1[f] = *(const float4*)(p0 + 8 * LDY);
        }
    };

    float4 a0[2], a1[2];
    load_frags(0, a0, a1);

#pragma unroll
    for (int c = 0; c < NC; c++) {
        float4 na0[2], na1[2];
        if (c + 1 < NC) load_frags(c + 1, na0, na1);
        mma_chunk_batched<N, NT>(acc, Wp + (size_t)c * (N * 16), a0, a1, n_idx, q, g4);
        if (c + 1 < NC) {
            a0[0] = na0[0]; a0[1] = na0[1];
            a1[0] = na1[0]; a1[1] = na1[1];
        }
    }
    __syncthreads();   // all Ys reads done before epilogue overwrites Ys

    epilogue_store<N, ROUND, NT>(acc, bg, Ys, m_idx, n_idx, q, g4);
    __syncthreads();
}

// ---------------- fused kernel ----------------
__global__ void __launch_bounds__(512, 1)
aev_mlp_mma(const float* __restrict__ fullaev, const int* __restrict__ species,
            const float* __restrict__ b0, const float* __restrict__ b1,
            const float* __restrict__ b2,
            const float* __restrict__ W3, const float* __restrict__ b3)
{
    extern __shared__ float sm[];
    float* Ys = sm;
    const float* XcF = sm;                  // X ring overlays Ys during L0
    const uint32_t xcU = smem_u32(sm);

    const int a = blockIdx.y;
    const int bbase = blockIdx.x * 128;
    const int tid = threadIdx.x;
    const int lane = tid & 31, wid = tid >> 5;
    const int m_idx = wid >> 2, n_idx = wid & 3;
    const int s = species[a];
    const float* xg = fullaev + (size_t)bbase * 98304 + (size_t)a * 384;

    layer0_run(g_Wp0 + (size_t)s * (24 * 256 * 16), b0 + s * 256, xg,
               Ys, XcF, xcU, tid, lane, m_idx, n_idx);
    layerR_run<256, 192, true >(g_Wp1 + (size_t)s * (16 * 192 * 16), b1 + s * 192,
                                Ys, lane, m_idx, n_idx);
    layerR_run<192, 160, false>(g_Wp2 + (size_t)s * (12 * 160 * 16), b2 + s * 160,
                                Ys, lane, m_idx, n_idx);

    // ---- layer 3: dot(Y2[r, 0:160], w3) + b3, celu (perm identity: p=4j+b <-> k=4b+j) ----
    if (tid < 128) {
        const float* w = W3 + s * 160;
        float s0 = 0.f, s1 = 0.f, s2 = 0.f, s3 = 0.f;
        const float* yr = Ys + tid * LDY;
#pragma unroll
        for (int gb = 0; gb < 160; gb += 16) {
            float4 y0 = *(const float4*)(yr + gb);
            float4 y1 = *(const float4*)(yr + gb + 4);
            float4 y2 = *(const float4*)(yr + gb + 8);
            float4 y3 = *(const float4*)(yr + gb + 12);
            // y_j.{x,y,z,w} = Y[k = gb + 4*{0,1,2,3} + j]
            s0 = fmaf(y0.x, __ldg(w + gb + 0),  s0);
            s0 = fmaf(y0.y, __ldg(w + gb + 4),  s0);
            s0 = fmaf(y0.z, __ldg(w + gb + 8),  s0);
            s0 = fmaf(y0.w, __ldg(w + gb + 12), s0);
            s1 = fmaf(y1.x, __ldg(w + gb + 1),  s1);
            s1 = fmaf(y1.y, __ldg(w + gb + 5),  s1);
            s1 = fmaf(y1.z, __ldg(w + gb + 9),  s1);
            s1 = fmaf(y1.w, __ldg(w + gb + 13), s1);
            s2 = fmaf(y2.x, __ldg(w + gb + 2),  s2);
            s2 = fmaf(y2.y, __ldg(w + gb + 6),  s2);
            s2 = fmaf(y2.z, __ldg(w + gb + 10), s2);
            s2 = fmaf(y2.w, __ldg(w + gb + 14), s2);
            s3 = fmaf(y3.x, __ldg(w + gb + 3),  s3);
            s3 = fmaf(y3.y, __ldg(w + gb + 7),  s3);
            s3 = fmaf(y3.z, __ldg(w + gb + 11), s3);
            s3 = fmaf(y3.w, __ldg(w + gb + 15), s3);
        }
        float acc = ((s0 + s1) + (s2 + s3)) + __ldg(b3 + s);
        g_partial[(size_t)a * 1024 + bbase + tid] = celu_f(acc);
    }
}

// ---------------- deterministic two-stage reduction ----------------
__global__ void reduce1() {
    int b = blockIdx.x * 256 + threadIdx.x;
    int ag = blockIdx.y;
    float acc = 0.f;
#pragma unroll
    for (int i = 0; i < 32; i++) acc += g_partial[(size_t)(ag * 32 + i) * 1024 + b];
    g_red[ag * 1024 + b] = acc;
}
__global__ void reduce2(float* __restrict__ out) {
    int b = blockIdx.x * 256 + threadIdx.x;
    float acc = 0.f;
#pragma unroll
    for (int g = 0; g < 8; g++) acc += g_red[g * 1024 + b];
    out[b] = acc;
}

extern "C" void kernel_launch(void* const* d_in, const int* in_sizes, int n_in,
                              void* d_out, int out_size) {
    const float* fullaev = (const float*)d_in[0];
    const int*   species = (const int*)d_in[1];
    const float* W0 = (const float*)d_in[2];
    const float* b0 = (const float*)d_in[3];
    const float* W1 = (const float*)d_in[4];
    const float* b1 = (const float*)d_in[5];
    const float* W2 = (const float*)d_in[6];
    const float* b2 = (const float*)d_in[7];
    const float* W3 = (const float*)d_in[8];
    const float* b3 = (const float*)d_in[9];

    prep_w<384, 256, 0><<<(4 * 384 * 256 + 255) / 256, 256>>>(W0);
    prep_w<256, 192, 1><<<(4 * 256 * 192 + 255) / 256, 256>>>(W1);
    prep_w<192, 160, 2><<<(4 * 192 * 160 + 255) / 256, 256>>>(W2);

    cudaFuncSetAttribute(aev_mlp_mma, cudaFuncAttributeMaxDynamicSharedMemorySize, SMEM_BYTES);
    dim3 grid(8, 256);   // (B-tiles of 128, atoms)
    aev_mlp_mma<<<grid, 512, SMEM_BYTES>>>(fullaev, species, b0, b1, b2, W3, b3);

    reduce1<<<dim3(4, 8), 256>>>();
    reduce2<<<4, 256>>>((float*)d_out);
}